// round 6
// baseline (speedup 1.0000x reference)
#include <cuda_runtime.h>
#include <math.h>
#include <stdint.h>

#define BB 4
#define NN 4096
#define NFF 8192
#define KK 512
#define CC 128
#define LL 4
#define INDIM 3
#define FCD 128
#define FWD_S 4   // split-N factor for forward GEMM

// -------- scratch (device globals) --------
__device__ float g_Bc[BB*KK*NN];           // cos basis (32 MB)
__device__ float g_Bs[BB*KK*NN];           // sin basis (32 MB)
__device__ float g_wqn[BB*NN];
__device__ float g_h[2][BB*CC*NN];         // ping-pong hidden state
__device__ float g_hw[BB*CC*NN];           // h0 * wqn
__device__ float g_xch[BB*CC*KK];
__device__ float g_xsp[BB*CC*KK];
__device__ float g_pc[FWD_S][BB*CC*KK];    // forward partials
__device__ float g_ps[FWD_S][BB*CC*KK];
__device__ float g_fA[LL][BB*CC*KK];       //  2*fch/nf  per layer
__device__ float g_fB[LL][BB*CC*KK];       // -2*fsh/nf  per layer
__device__ float g_x1[LL][BB*CC*NN];       // spectral inverse per layer
__device__ float g_x0h[BB*CC];
__device__ float g_f0h[LL][BB*CC];

__device__ __forceinline__ float gelu_exact(float v) {
    return 0.5f * v * (1.0f + erff(v * 0.7071067811865476f));
}
__device__ __forceinline__ float tf32r(float x) {
    float r;
    asm("cvt.rna.tf32.f32 %0, %1;" : "=f"(r) : "f"(x));
    return r;
}
__device__ __forceinline__ void split_tf32(float v, float& hi, float& lo) {
    hi = tf32r(v);
    lo = tf32r(v - hi);
}
// tf32 mma: D(16x8) += A(16x8) * B(8x8), fp32 accum
__device__ __forceinline__ void mma_tf32(float (&d)[4], const uint32_t (&a)[4],
                                         const uint32_t (&b)[2]) {
    asm volatile(
        "mma.sync.aligned.m16n8k8.row.col.f32.tf32.tf32.f32 "
        "{%0,%1,%2,%3}, {%4,%5,%6,%7}, {%8,%9}, {%0,%1,%2,%3};"
        : "+f"(d[0]), "+f"(d[1]), "+f"(d[2]), "+f"(d[3])
        : "r"(a[0]), "r"(a[1]), "r"(a[2]), "r"(a[3]), "r"(b[0]), "r"(b[1]));
}

// -------- K1: basis precompute --------
__global__ void k_basis(const float* __restrict__ xf, const int* __restrict__ ind,
                        const float* __restrict__ modes) {
    int idx = blockIdx.x * blockDim.x + threadIdx.x;
    if (idx >= BB*KK*NN) return;
    int n = idx & (NN - 1);
    int k = (idx >> 12) & (KK - 1);
    int b = idx >> 21;
    int f = __ldg(&ind[n]);
    const float* xfp = xf + ((size_t)b * NFF + f) * 4;
    float gx = __ldg(&xfp[0]);
    float gy = __ldg(&xfp[1]);
    float wq = __ldg(&xfp[2]);
    float mx = __ldg(&modes[2*k]);
    float my = __ldg(&modes[2*k+1]);
    float t = gx * mx + gy * my;
    float s, c;
    __sincosf(t, &s, &c);
    g_Bc[idx] = c;
    g_Bs[idx] = s;
    if (k == 0) g_wqn[b*NN + n] = wq * (float)NN;
}

// -------- K2: fc0 --------
__global__ void k_fc0(const float* __restrict__ x, const float* __restrict__ w,
                      const float* __restrict__ bias) {
    int n = blockIdx.x * blockDim.x + threadIdx.x;
    int c = blockIdx.y;
    int b = blockIdx.z;
    const float* xp = x + ((size_t)b * NN + n) * INDIM;
    float acc = bias[c]
              + xp[0] * w[0*CC + c]
              + xp[1] * w[1*CC + c]
              + xp[2] * w[2*CC + c];
    size_t o = ((size_t)b*CC + c) * NN + n;
    g_h[0][o] = acc;
    g_hw[o]   = acc * g_wqn[b*NN + n];
}

// -------- K2b: x0h reduce (once) --------
__global__ void k_x0h() {
    int bc = blockIdx.x;
    const float* p = g_hw + (size_t)bc * NN;
    float acc = 0.f;
    for (int n = threadIdx.x; n < NN; n += 256) acc += p[n];
    __shared__ float red[256];
    red[threadIdx.x] = acc;
    __syncthreads();
    for (int s = 128; s > 0; s >>= 1) {
        if (threadIdx.x < s) red[threadIdx.x] += red[threadIdx.x + s];
        __syncthreads();
    }
    if (threadIdx.x == 0) g_x0h[bc] = red[0];
}

// -------- K3: forward dual GEMM, tf32 TC, split-N partials --------
__global__ void k_fwd_tc() {
    __shared__ float As[32][36];
    __shared__ float Bsm[2][64][36];
    int z   = blockIdx.z;
    int b   = z >> 2;
    int s   = z & 3;
    int m0  = blockIdx.y * 32;
    int ko0 = blockIdx.x * 64;
    int tid = threadIdx.x;
    int lane = tid & 31, wid = tid >> 5;
    int wm = wid >> 2, wn = wid & 3;
    int g = lane >> 2, tig = lane & 3;
    float acc[2][2][4] = {};
    const float* A  = g_hw + ((size_t)b*CC + m0) * NN + s * (NN/FWD_S);
    const float* Bc = g_Bc + ((size_t)b*KK + ko0) * NN + s * (NN/FWD_S);
    const float* Bs = g_Bs + ((size_t)b*KK + ko0) * NN + s * (NN/FWD_S);
    int arow = tid >> 3, ac4 = (tid & 7) * 4;
    for (int r0 = 0; r0 < NN/FWD_S; r0 += 32) {
        *(float4*)&As[arow][ac4] = *(const float4*)&A[(size_t)arow*NN + r0 + ac4];
        #pragma unroll
        for (int t = 0; t < 2; t++) {
            int idx = tid + t*256;
            int brow = idx >> 3, bc4 = (idx & 7) * 4;
            *(float4*)&Bsm[0][brow][bc4] = *(const float4*)&Bc[(size_t)brow*NN + r0 + bc4];
            *(float4*)&Bsm[1][brow][bc4] = *(const float4*)&Bs[(size_t)brow*NN + r0 + bc4];
        }
        __syncthreads();
        #pragma unroll
        for (int kk = 0; kk < 32; kk += 8) {
            uint32_t af[4];
            int m = wm * 16;
            af[0] = __float_as_uint(As[m+g  ][kk+tig  ]);
            af[1] = __float_as_uint(As[m+g+8][kk+tig  ]);
            af[2] = __float_as_uint(As[m+g  ][kk+tig+4]);
            af[3] = __float_as_uint(As[m+g+8][kk+tig+4]);
            #pragma unroll
            for (int p = 0; p < 2; p++) {
                #pragma unroll
                for (int ns = 0; ns < 2; ns++) {
                    int n = wn * 16 + ns * 8;
                    uint32_t bf[2];
                    bf[0] = __float_as_uint(Bsm[p][n+g][kk+tig  ]);
                    bf[1] = __float_as_uint(Bsm[p][n+g][kk+tig+4]);
                    mma_tf32(acc[p][ns], af, bf);
                }
            }
        }
        __syncthreads();
    }
    #pragma unroll
    for (int ns = 0; ns < 2; ns++) {
        int m = m0 + wm*16 + g;
        int k = ko0 + wn*16 + ns*8 + tig*2;
        size_t o0 = ((size_t)b*CC + m)*KK + k;
        size_t o1 = ((size_t)b*CC + m + 8)*KK + k;
        g_pc[s][o0]   = acc[0][ns][0];
        g_pc[s][o0+1] = acc[0][ns][1];
        g_pc[s][o1]   = acc[0][ns][2];
        g_pc[s][o1+1] = acc[0][ns][3];
        g_ps[s][o0]   = acc[1][ns][0];
        g_ps[s][o0+1] = acc[1][ns][1];
        g_ps[s][o1]   = acc[1][ns][2];
        g_ps[s][o1+1] = acc[1][ns][3];
    }
}

__global__ void k_fwd_red() {
    int i = (blockIdx.x * 256 + threadIdx.x) * 4;
    float4 c0 = *(const float4*)&g_pc[0][i];
    float4 c1 = *(const float4*)&g_pc[1][i];
    float4 c2 = *(const float4*)&g_pc[2][i];
    float4 c3 = *(const float4*)&g_pc[3][i];
    float4 s0 = *(const float4*)&g_ps[0][i];
    float4 s1 = *(const float4*)&g_ps[1][i];
    float4 s2 = *(const float4*)&g_ps[2][i];
    float4 s3 = *(const float4*)&g_ps[3][i];
    float4 c, s;
    c.x = (c0.x+c1.x)+(c2.x+c3.x); c.y = (c0.y+c1.y)+(c2.y+c3.y);
    c.z = (c0.z+c1.z)+(c2.z+c3.z); c.w = (c0.w+c1.w)+(c2.w+c3.w);
    s.x = (s0.x+s1.x)+(s2.x+s3.x); s.y = (s0.y+s1.y)+(s2.y+s3.y);
    s.z = (s0.z+s1.z)+(s2.z+s3.z); s.w = (s0.w+s1.w)+(s2.w+s3.w);
    *(float4*)&g_xch[i] = c;
    *(float4*)&g_xsp[i] = s;
}

// -------- K4: mode mix, all layers, float4 over k --------
__global__ void k_mix_all(const float* __restrict__ wc, const float* __restrict__ ws) {
    int o = blockIdx.x;              // 0..127
    int l = blockIdx.y;              // 0..3
    int k = threadIdx.x * 4;         // 0..508
    const float inv_nf = 1.0f / (float)NFF;
    float4 accc[BB], accs[BB];
    #pragma unroll
    for (int b = 0; b < BB; b++) {
        accc[b] = make_float4(0.f,0.f,0.f,0.f);
        accs[b] = make_float4(0.f,0.f,0.f,0.f);
    }
    const float* wcp = wc + (((size_t)l*CC)*CC + o)*KK + k;
    const float* wsp = ws + (((size_t)l*CC)*CC + o)*KK + k;
    #pragma unroll 2
    for (int i = 0; i < CC; i++) {
        float4 wcv = *(const float4*)(wcp + (size_t)i*CC*KK);
        float4 wsv = *(const float4*)(wsp + (size_t)i*CC*KK);
        #pragma unroll
        for (int b = 0; b < BB; b++) {
            float4 xc = *(const float4*)(g_xch + ((size_t)b*CC + i)*KK + k);
            float4 xs = *(const float4*)(g_xsp + ((size_t)b*CC + i)*KK + k);
            accc[b].x += xc.x*wcv.x + xs.x*wsv.x;
            accc[b].y += xc.y*wcv.y + xs.y*wsv.y;
            accc[b].z += xc.z*wcv.z + xs.z*wsv.z;
            accc[b].w += xc.w*wcv.w + xs.w*wsv.w;
            accs[b].x += xc.x*wsv.x - xs.x*wcv.x;
            accs[b].y += xc.y*wsv.y - xs.y*wcv.y;
            accs[b].z += xc.z*wsv.z - xs.z*wcv.z;
            accs[b].w += xc.w*wsv.w - xs.w*wcv.w;
        }
    }
    #pragma unroll
    for (int b = 0; b < BB; b++) {
        float4 fa, fb;
        fa.x =  2.0f*inv_nf*accc[b].x; fa.y =  2.0f*inv_nf*accc[b].y;
        fa.z =  2.0f*inv_nf*accc[b].z; fa.w =  2.0f*inv_nf*accc[b].w;
        fb.x = -2.0f*inv_nf*accs[b].x; fb.y = -2.0f*inv_nf*accs[b].y;
        fb.z = -2.0f*inv_nf*accs[b].z; fb.w = -2.0f*inv_nf*accs[b].w;
        *(float4*)&g_fA[l][((size_t)b*CC + o)*KK + k] = fa;
        *(float4*)&g_fB[l][((size_t)b*CC + o)*KK + k] = fb;
    }
}

// -------- K4b: f0h, all layers --------
__global__ void k_f0h_all(const float* __restrict__ w0, const float* __restrict__ convb) {
    int l = blockIdx.x;
    int t = threadIdx.x;
    int b = t >> 7, o = t & 127;
    float acc = 0.f;
    #pragma unroll 4
    for (int i = 0; i < CC; i++)
        acc += g_x0h[b*CC + i] * __ldg(&w0[((size_t)l*CC + i)*CC + o]);
    g_f0h[l][t] = acc * (1.0f / (float)NFF) + convb[l*CC + o];
}

// -------- K5a: inverse spectral GEMM, 2 layers per block, tf32 TC --------
// B tiles (Bc/Bs) shared across the layer pair: halves B traffic + B LDS.
__global__ void __launch_bounds__(256, 2) k_inv_spec2() {
    __shared__ float As[4][64][20];     // [l2*2+p][m][k]
    __shared__ float Bsm[2][16][132];
    int z  = blockIdx.z;                // b*2 + lp
    int b  = z >> 1;
    int lp = z & 1;
    int m0 = blockIdx.y * 64;
    int n0 = blockIdx.x * 128;
    int tid = threadIdx.x;
    int lane = tid & 31, wid = tid >> 5;
    int wm = wid >> 2, wn = wid & 3;
    int g = lane >> 2, tig = lane & 3;
    float acc[2][2][4][4] = {};         // [l2][ms][ns][4]
    const float* Aptr[4];
    Aptr[0] = g_fA[2*lp]   + ((size_t)b*CC + m0)*KK;
    Aptr[1] = g_fB[2*lp]   + ((size_t)b*CC + m0)*KK;
    Aptr[2] = g_fA[2*lp+1] + ((size_t)b*CC + m0)*KK;
    Aptr[3] = g_fB[2*lp+1] + ((size_t)b*CC + m0)*KK;
    const float* Bc = g_Bc + (size_t)b*KK*NN;
    const float* Bs = g_Bs + (size_t)b*KK*NN;
    int arow = tid >> 2, ac4 = (tid & 3) * 4;
    for (int r0 = 0; r0 < KK; r0 += 16) {
        #pragma unroll
        for (int q = 0; q < 4; q++)
            *(float4*)&As[q][arow][ac4] = *(const float4*)&Aptr[q][(size_t)arow*KK + r0 + ac4];
        #pragma unroll
        for (int t = 0; t < 2; t++) {
            int idx = tid + t*256;
            int brow = idx >> 5, bc4 = (idx & 31) * 4;
            *(float4*)&Bsm[0][brow][bc4] = *(const float4*)&Bc[(size_t)(r0+brow)*NN + n0 + bc4];
            *(float4*)&Bsm[1][brow][bc4] = *(const float4*)&Bs[(size_t)(r0+brow)*NN + n0 + bc4];
        }
        __syncthreads();
        #pragma unroll
        for (int kk = 0; kk < 16; kk += 8) {
            #pragma unroll
            for (int p = 0; p < 2; p++) {
                uint32_t bf[4][2];
                #pragma unroll
                for (int ns = 0; ns < 4; ns++) {
                    int n = wn*32 + ns*8;
                    bf[ns][0] = __float_as_uint(Bsm[p][kk+tig  ][n+g]);
                    bf[ns][1] = __float_as_uint(Bsm[p][kk+tig+4][n+g]);
                }
                #pragma unroll
                for (int l2 = 0; l2 < 2; l2++) {
                    int q = l2*2 + p;
                    uint32_t af[2][4];
                    #pragma unroll
                    for (int ms = 0; ms < 2; ms++) {
                        int m = wm*32 + ms*16;
                        af[ms][0] = __float_as_uint(As[q][m+g  ][kk+tig  ]);
                        af[ms][1] = __float_as_uint(As[q][m+g+8][kk+tig  ]);
                        af[ms][2] = __float_as_uint(As[q][m+g  ][kk+tig+4]);
                        af[ms][3] = __float_as_uint(As[q][m+g+8][kk+tig+4]);
                    }
                    #pragma unroll
                    for (int ns = 0; ns < 4; ns++)
                        #pragma unroll
                        for (int ms = 0; ms < 2; ms++)
                            mma_tf32(acc[l2][ms][ns], af[ms], bf[ns]);
                }
            }
        }
        __syncthreads();
    }
    #pragma unroll
    for (int l2 = 0; l2 < 2; l2++) {
        float* X1 = g_x1[2*lp + l2] + (size_t)b*CC*NN;
        #pragma unroll
        for (int ms = 0; ms < 2; ms++) {
            #pragma unroll
            for (int ns = 0; ns < 4; ns++) {
                int m = m0 + wm*32 + ms*16 + g;
                int n = n0 + wn*32 + ns*8 + tig*2;
                X1[(size_t)m*NN + n]         = acc[l2][ms][ns][0];
                X1[(size_t)m*NN + n + 1]     = acc[l2][ms][ns][1];
                X1[(size_t)(m+8)*NN + n]     = acc[l2][ms][ns][2];
                X1[(size_t)(m+8)*NN + n + 1] = acc[l2][ms][ns][3];
            }
        }
    }
}

// -------- K5b: conv via 3xTF32 tensor cores + epilogue --------
__global__ void k_conv_tc(const float* __restrict__ convw, int l, int cur) {
    __shared__ float Ah[64][20], Al[64][20];
    __shared__ float Bh[16][132], Bl[16][132];
    int b  = blockIdx.z;
    int m0 = blockIdx.y * 64;
    int n0 = blockIdx.x * 128;
    int tid = threadIdx.x;
    int lane = tid & 31, wid = tid >> 5;
    int wm = wid >> 2, wn = wid & 3;
    int g = lane >> 2, tig = lane & 3;
    float acc[2][4][4] = {};
    const float* W = convw + (size_t)l*CC*CC + (size_t)m0*CC;
    const float* H = g_h[cur] + (size_t)b*CC*NN;
    int arow = tid >> 2, ac4 = (tid & 3) * 4;
    for (int r0 = 0; r0 < CC; r0 += 16) {
        float4 va = *(const float4*)&W[(size_t)arow*CC + r0 + ac4];
        float h0,l0,h1,l1,h2,l2,h3,l3;
        split_tf32(va.x, h0, l0); split_tf32(va.y, h1, l1);
        split_tf32(va.z, h2, l2); split_tf32(va.w, h3, l3);
        Ah[arow][ac4] = h0; Ah[arow][ac4+1] = h1; Ah[arow][ac4+2] = h2; Ah[arow][ac4+3] = h3;
        Al[arow][ac4] = l0; Al[arow][ac4+1] = l1; Al[arow][ac4+2] = l2; Al[arow][ac4+3] = l3;
        #pragma unroll
        for (int t = 0; t < 2; t++) {
            int idx = tid + t*256;
            int brow = idx >> 5, bc4 = (idx & 31) * 4;
            float4 vb = *(const float4*)&H[(size_t)(r0+brow)*NN + n0 + bc4];
            float bh0,bl0,bh1,bl1,bh2,bl2,bh3,bl3;
            split_tf32(vb.x, bh0, bl0); split_tf32(vb.y, bh1, bl1);
            split_tf32(vb.z, bh2, bl2); split_tf32(vb.w, bh3, bl3);
            Bh[brow][bc4] = bh0; Bh[brow][bc4+1] = bh1; Bh[brow][bc4+2] = bh2; Bh[brow][bc4+3] = bh3;
            Bl[brow][bc4] = bl0; Bl[brow][bc4+1] = bl1; Bl[brow][bc4+2] = bl2; Bl[brow][bc4+3] = bl3;
        }
        __syncthreads();
        #pragma unroll
        for (int kk = 0; kk < 16; kk += 8) {
            uint32_t afh[2][4], afl[2][4];
            #pragma unroll
            for (int ms = 0; ms < 2; ms++) {
                int m = wm*32 + ms*16;
                afh[ms][0] = __float_as_uint(Ah[m+g  ][kk+tig  ]);
                afh[ms][1] = __float_as_uint(Ah[m+g+8][kk+tig  ]);
                afh[ms][2] = __float_as_uint(Ah[m+g  ][kk+tig+4]);
                afh[ms][3] = __float_as_uint(Ah[m+g+8][kk+tig+4]);
                afl[ms][0] = __float_as_uint(Al[m+g  ][kk+tig  ]);
                afl[ms][1] = __float_as_uint(Al[m+g+8][kk+tig  ]);
                afl[ms][2] = __float_as_uint(Al[m+g  ][kk+tig+4]);
                afl[ms][3] = __float_as_uint(Al[m+g+8][kk+tig+4]);
            }
            #pragma unroll
            for (int ns = 0; ns < 4; ns++) {
                int n = wn*32 + ns*8;
                uint32_t bfh[2], bfl[2];
                bfh[0] = __float_as_uint(Bh[kk+tig  ][n+g]);
                bfh[1] = __float_as_uint(Bh[kk+tig+4][n+g]);
                bfl[0] = __float_as_uint(Bl[kk+tig  ][n+g]);
                bfl[1] = __float_as_uint(Bl[kk+tig+4][n+g]);
                #pragma unroll
                for (int ms = 0; ms < 2; ms++) {
                    mma_tf32(acc[ms][ns], afh[ms], bfh);
                    mma_tf32(acc[ms][ns], afh[ms], bfl);
                    mma_tf32(acc[ms][ns], afl[ms], bfh);
                }
            }
        }
        __syncthreads();
    }
    int nxt = cur ^ 1;
    const float* X1 = g_x1[l] + (size_t)b*CC*NN;
    float* Hn = g_h[nxt] + (size_t)b*CC*NN;
    #pragma unroll
    for (int ms = 0; ms < 2; ms++) {
        #pragma unroll
        for (int ns = 0; ns < 4; ns++) {
            int m = m0 + wm*32 + ms*16 + g;
            int n = n0 + wn*32 + ns*8 + tig*2;
            float bias0 = g_f0h[l][b*CC + m];
            float bias1 = g_f0h[l][b*CC + m + 8];
            float v0 = acc[ms][ns][0] + bias0 + X1[(size_t)m*NN + n];
            float v1 = acc[ms][ns][1] + bias0 + X1[(size_t)m*NN + n + 1];
            float v2 = acc[ms][ns][2] + bias1 + X1[(size_t)(m+8)*NN + n];
            float v3 = acc[ms][ns][3] + bias1 + X1[(size_t)(m+8)*NN + n + 1];
            if (l < LL - 1) {
                v0 = gelu_exact(v0); v1 = gelu_exact(v1);
                v2 = gelu_exact(v2); v3 = gelu_exact(v3);
            }
            Hn[(size_t)m*NN + n]         = v0;
            Hn[(size_t)m*NN + n + 1]     = v1;
            Hn[(size_t)(m+8)*NN + n]     = v2;
            Hn[(size_t)(m+8)*NN + n + 1] = v3;
        }
    }
}

// -------- K6: head --------
__global__ void k_head(const float* __restrict__ w1, const float* __restrict__ b1,
                       const float* __restrict__ w2, const float* __restrict__ b2,
                       float* __restrict__ out, int cur) {
    __shared__ float sh[CC][32];
    __shared__ float red[CC][33];
    int b  = blockIdx.y;
    int n0 = blockIdx.x * 32;
    int f = threadIdx.x;  // 0..127
    const float* H = g_h[cur] + (size_t)b*CC*NN + n0;
    #pragma unroll 4
    for (int c4 = 0; c4 < CC; c4 += 4) {
        int row = c4 + (f >> 5);
        int col = f & 31;
        sh[row][col] = H[(size_t)row*NN + col];
    }
    __syncthreads();
    float acc[32];
    float bv = b1[f];
    #pragma unroll
    for (int j = 0; j < 32; j++) acc[j] = bv;
    for (int c = 0; c < CC; c++) {
        float w = __ldg(&w1[(size_t)c*FCD + f]);
        #pragma unroll
        for (int j = 0; j < 32; j++) acc[j] += sh[c][j] * w;
    }
    float w2f = __ldg(&w2[f]);
    #pragma unroll
    for (int j = 0; j < 32; j++)
        red[f][j] = gelu_exact(acc[j]) * w2f;
    __syncthreads();
    if (f < 32) {
        float s = b2[0];
        #pragma unroll 8
        for (int q = 0; q < CC; q++) s += red[q][f];
        out[(size_t)b*NN + n0 + f] = s;
    }
}

// -------- launch --------
extern "C" void kernel_launch(void* const* d_in, const int* in_sizes, int n_in,
                              void* d_out, int out_size) {
    (void)in_sizes; (void)n_in; (void)out_size;
    const float* x     = (const float*)d_in[0];
    const float* xf    = (const float*)d_in[1];
    const int*   ind   = (const int*)  d_in[2];
    const float* modes = (const float*)d_in[3];
    const float* fc0_w = (const float*)d_in[4];
    const float* fc0_b = (const float*)d_in[5];
    const float* wc    = (const float*)d_in[6];
    const float* ws    = (const float*)d_in[7];
    const float* w0    = (const float*)d_in[8];
    const float* convw = (const float*)d_in[9];
    const float* convb = (const float*)d_in[10];
    const float* fc1_w = (const float*)d_in[11];
    const float* fc1_b = (const float*)d_in[12];
    const float* fc2_w = (const float*)d_in[13];
    const float* fc2_b = (const float*)d_in[14];
    float* out = (float*)d_out;

    k_basis<<<(BB*KK*NN + 255)/256, 256>>>(xf, ind, modes);

    dim3 g2(NN/256, CC, BB);
    k_fc0<<<g2, 256>>>(x, fc0_w, fc0_b);

    // forward spectral transform (loop-invariant): split-N + reduce
    k_x0h<<<BB*CC, 256>>>();
    dim3 g3(KK/64, CC/32, BB*FWD_S);
    k_fwd_tc<<<g3, 256>>>();
    k_fwd_red<<<BB*CC*KK/1024, 256>>>();

    // all layers' spectral work is independent of the h-chain: batch it
    dim3 g4(CC, LL);
    k_mix_all<<<g4, 128>>>(wc, ws);
    k_f0h_all<<<LL, BB*CC>>>(w0, convb);
    dim3 g5(NN/128, CC/64, BB*2);
    k_inv_spec2<<<g5, 256>>>();

    // sequential conv chain (3xTF32 tensor cores)
    int cur = 0;
    for (int l = 0; l < LL; l++) {
        dim3 g6(NN/128, CC/64, BB);
        k_conv_tc<<<g6, 256>>>(convw, l, cur);
        cur ^= 1;
    }

    dim3 g7(NN/32, BB);
    k_head<<<g7, 128>>>(fc1_w, fc1_b, fc2_w, fc2_b, out, cur);
}

// round 7
// speedup vs baseline: 1.1890x; 1.1890x over previous
#include <cuda_runtime.h>
#include <cuda_bf16.h>
#include <math.h>
#include <stdint.h>

#define BB 4
#define NN 4096
#define NFF 8192
#define KK 512
#define CC 128
#define LL 4
#define INDIM 3
#define FCD 128
#define FWD_S 4

typedef __nv_bfloat16 bf16;
typedef __nv_bfloat162 bf162;

// -------- scratch --------
__device__ bf16  g_Bc [BB*KK*NN];      // basis [b][k][n]  (16 MB)
__device__ bf16  g_Bs [BB*KK*NN];
__device__ bf16  g_BcT[BB*NN*KK];      // basis [b][n][k]  (16 MB)
__device__ bf16  g_BsT[BB*NN*KK];
__device__ float g_wqn[BB*NN];
__device__ float g_h[2][BB*CC*NN];
__device__ float g_hw[BB*CC*NN];       // h0*wqn f32 (for x0h)
__device__ bf16  g_hwb[BB*CC*NN];      // h0*wqn bf16 (for fwd mma)
__device__ float g_xch[BB*CC*KK];
__device__ float g_xsp[BB*CC*KK];
__device__ float g_pc[FWD_S][BB*CC*KK];
__device__ float g_ps[FWD_S][BB*CC*KK];
__device__ bf16  g_fAb[LL][BB*CC*KK];  //  2*fch/nf bf16
__device__ bf16  g_fBb[LL][BB*CC*KK];  // -2*fsh/nf bf16
__device__ float g_x1[LL][BB*CC*NN];
__device__ float g_x0h[BB*CC];
__device__ float g_f0h[LL][BB*CC];

__device__ __forceinline__ float gelu_exact(float v) {
    return 0.5f * v * (1.0f + erff(v * 0.7071067811865476f));
}
__device__ __forceinline__ float tf32r(float x) {
    float r;
    asm("cvt.rna.tf32.f32 %0, %1;" : "=f"(r) : "f"(x));
    return r;
}
__device__ __forceinline__ void split_tf32(float v, float& hi, float& lo) {
    hi = tf32r(v);
    lo = tf32r(v - hi);
}
__device__ __forceinline__ void mma_tf32(float (&d)[4], const uint32_t (&a)[4],
                                         const uint32_t (&b)[2]) {
    asm volatile(
        "mma.sync.aligned.m16n8k8.row.col.f32.tf32.tf32.f32 "
        "{%0,%1,%2,%3}, {%4,%5,%6,%7}, {%8,%9}, {%0,%1,%2,%3};"
        : "+f"(d[0]), "+f"(d[1]), "+f"(d[2]), "+f"(d[3])
        : "r"(a[0]), "r"(a[1]), "r"(a[2]), "r"(a[3]), "r"(b[0]), "r"(b[1]));
}
__device__ __forceinline__ void mma_bf16(float (&d)[4], const uint32_t (&a)[4],
                                         const uint32_t (&b)[2]) {
    asm volatile(
        "mma.sync.aligned.m16n8k16.row.col.f32.bf16.bf16.f32 "
        "{%0,%1,%2,%3}, {%4,%5,%6,%7}, {%8,%9}, {%0,%1,%2,%3};"
        : "+f"(d[0]), "+f"(d[1]), "+f"(d[2]), "+f"(d[3])
        : "r"(a[0]), "r"(a[1]), "r"(a[2]), "r"(a[3]), "r"(b[0]), "r"(b[1]));
}

// -------- K1: basis precompute (bf16 stores) --------
__global__ void k_basis(const float* __restrict__ xf, const int* __restrict__ ind,
                        const float* __restrict__ modes) {
    int idx = blockIdx.x * blockDim.x + threadIdx.x;
    if (idx >= BB*KK*NN) return;
    int n = idx & (NN - 1);
    int k = (idx >> 12) & (KK - 1);
    int b = idx >> 21;
    int f = __ldg(&ind[n]);
    const float* xfp = xf + ((size_t)b * NFF + f) * 4;
    float gx = __ldg(&xfp[0]);
    float gy = __ldg(&xfp[1]);
    float wq = __ldg(&xfp[2]);
    float mx = __ldg(&modes[2*k]);
    float my = __ldg(&modes[2*k+1]);
    float t = gx * mx + gy * my;
    float s, c;
    __sincosf(t, &s, &c);
    g_Bc[idx] = __float2bfloat16(c);
    g_Bs[idx] = __float2bfloat16(s);
    if (k == 0) g_wqn[b*NN + n] = wq * (float)NN;
}

// -------- K1b: transpose basis to [n][k] (one-time, memory-bound) --------
__global__ void k_bT() {
    __shared__ bf16 t0[32][33];
    __shared__ bf16 t1[32][33];
    int b  = blockIdx.z;
    int k0 = blockIdx.y * 32;
    int n0 = blockIdx.x * 32;
    int tx = threadIdx.x, ty = threadIdx.y;  // 32 x 8
    const bf16* sc = g_Bc + ((size_t)b*KK + k0)*NN + n0;
    const bf16* ss = g_Bs + ((size_t)b*KK + k0)*NN + n0;
    #pragma unroll
    for (int j = 0; j < 4; j++) {
        int r = ty*4 + j;
        t0[r][tx] = sc[(size_t)r*NN + tx];
        t1[r][tx] = ss[(size_t)r*NN + tx];
    }
    __syncthreads();
    bf16* dc = g_BcT + ((size_t)b*NN + n0)*KK + k0;
    bf16* ds = g_BsT + ((size_t)b*NN + n0)*KK + k0;
    #pragma unroll
    for (int j = 0; j < 4; j++) {
        int r = ty*4 + j;
        dc[(size_t)r*KK + tx] = t0[tx][r];
        ds[(size_t)r*KK + tx] = t1[tx][r];
    }
}

// -------- K2: fc0 --------
__global__ void k_fc0(const float* __restrict__ x, const float* __restrict__ w,
                      const float* __restrict__ bias) {
    int n = blockIdx.x * blockDim.x + threadIdx.x;
    int c = blockIdx.y;
    int b = blockIdx.z;
    const float* xp = x + ((size_t)b * NN + n) * INDIM;
    float acc = bias[c]
              + xp[0] * w[0*CC + c]
              + xp[1] * w[1*CC + c]
              + xp[2] * w[2*CC + c];
    size_t o = ((size_t)b*CC + c) * NN + n;
    float hw = acc * g_wqn[b*NN + n];
    g_h[0][o] = acc;
    g_hw[o]   = hw;
    g_hwb[o]  = __float2bfloat16(hw);
}

// -------- K2b: x0h --------
__global__ void k_x0h() {
    int bc = blockIdx.x;
    const float* p = g_hw + (size_t)bc * NN;
    float acc = 0.f;
    for (int n = threadIdx.x; n < NN; n += 256) acc += p[n];
    __shared__ float red[256];
    red[threadIdx.x] = acc;
    __syncthreads();
    for (int s = 128; s > 0; s >>= 1) {
        if (threadIdx.x < s) red[threadIdx.x] += red[threadIdx.x + s];
        __syncthreads();
    }
    if (threadIdx.x == 0) g_x0h[bc] = red[0];
}

// -------- K3: forward dual GEMM, bf16 TC, split-N partials --------
// xch/xsp[b,c,ko] = sum_n hw[b,c,n] * Bc/Bs[b,ko,n] ; contraction n is contiguous
// in BOTH operands. block 32(m=c) x 64(n=ko), k-chunk 64.
__global__ void k_fwd_tc() {
    __shared__ bf16 As[32][72];
    __shared__ bf16 Bsm[2][64][72];
    int z   = blockIdx.z;
    int b   = z >> 2;
    int s   = z & 3;
    int m0  = blockIdx.y * 32;
    int ko0 = blockIdx.x * 64;
    int tid = threadIdx.x;
    int lane = tid & 31, wid = tid >> 5;
    int wm = wid >> 2, wn = wid & 3;
    int g = lane >> 2, tig = lane & 3;
    float acc[2][2][4] = {};
    const bf16* A  = g_hwb + ((size_t)b*CC + m0) * NN + s * (NN/FWD_S);
    const bf16* Bc = g_Bc  + ((size_t)b*KK + ko0) * NN + s * (NN/FWD_S);
    const bf16* Bs = g_Bs  + ((size_t)b*KK + ko0) * NN + s * (NN/FWD_S);
    int arow = tid >> 3, ac8 = (tid & 7) * 8;
    for (int r0 = 0; r0 < NN/FWD_S; r0 += 64) {
        *(uint4*)&As[arow][ac8] = *(const uint4*)&A[(size_t)arow*NN + r0 + ac8];
        #pragma unroll
        for (int t = 0; t < 2; t++) {
            int brow = (tid >> 3) + t*32;
            *(uint4*)&Bsm[0][brow][ac8] = *(const uint4*)&Bc[(size_t)brow*NN + r0 + ac8];
            *(uint4*)&Bsm[1][brow][ac8] = *(const uint4*)&Bs[(size_t)brow*NN + r0 + ac8];
        }
        __syncthreads();
        #pragma unroll
        for (int kk = 0; kk < 64; kk += 16) {
            uint32_t af[4];
            int m = wm * 16;
            af[0] = *(const uint32_t*)&As[m+g  ][kk + 2*tig    ];
            af[1] = *(const uint32_t*)&As[m+g+8][kk + 2*tig    ];
            af[2] = *(const uint32_t*)&As[m+g  ][kk + 2*tig + 8];
            af[3] = *(const uint32_t*)&As[m+g+8][kk + 2*tig + 8];
            #pragma unroll
            for (int p = 0; p < 2; p++) {
                #pragma unroll
                for (int ns = 0; ns < 2; ns++) {
                    int n = wn * 16 + ns * 8;
                    uint32_t bf[2];
                    bf[0] = *(const uint32_t*)&Bsm[p][n+g][kk + 2*tig    ];
                    bf[1] = *(const uint32_t*)&Bsm[p][n+g][kk + 2*tig + 8];
                    mma_bf16(acc[p][ns], af, bf);
                }
            }
        }
        __syncthreads();
    }
    #pragma unroll
    for (int ns = 0; ns < 2; ns++) {
        int m = m0 + wm*16 + g;
        int k = ko0 + wn*16 + ns*8 + tig*2;
        size_t o0 = ((size_t)b*CC + m)*KK + k;
        size_t o1 = ((size_t)b*CC + m + 8)*KK + k;
        g_pc[s][o0]   = acc[0][ns][0];
        g_pc[s][o0+1] = acc[0][ns][1];
        g_pc[s][o1]   = acc[0][ns][2];
        g_pc[s][o1+1] = acc[0][ns][3];
        g_ps[s][o0]   = acc[1][ns][0];
        g_ps[s][o0+1] = acc[1][ns][1];
        g_ps[s][o1]   = acc[1][ns][2];
        g_ps[s][o1+1] = acc[1][ns][3];
    }
}

__global__ void k_fwd_red() {
    int i = (blockIdx.x * 256 + threadIdx.x) * 4;
    float4 c0 = *(const float4*)&g_pc[0][i];
    float4 c1 = *(const float4*)&g_pc[1][i];
    float4 c2 = *(const float4*)&g_pc[2][i];
    float4 c3 = *(const float4*)&g_pc[3][i];
    float4 s0 = *(const float4*)&g_ps[0][i];
    float4 s1 = *(const float4*)&g_ps[1][i];
    float4 s2 = *(const float4*)&g_ps[2][i];
    float4 s3 = *(const float4*)&g_ps[3][i];
    float4 c, s;
    c.x = (c0.x+c1.x)+(c2.x+c3.x); c.y = (c0.y+c1.y)+(c2.y+c3.y);
    c.z = (c0.z+c1.z)+(c2.z+c3.z); c.w = (c0.w+c1.w)+(c2.w+c3.w);
    s.x = (s0.x+s1.x)+(s2.x+s3.x); s.y = (s0.y+s1.y)+(s2.y+s3.y);
    s.z = (s0.z+s1.z)+(s2.z+s3.z); s.w = (s0.w+s1.w)+(s2.w+s3.w);
    *(float4*)&g_xch[i] = c;
    *(float4*)&g_xsp[i] = s;
}

// -------- K4: mode mix, all layers, float4 over k, bf16 outputs --------
__global__ void k_mix_all(const float* __restrict__ wc, const float* __restrict__ ws) {
    int o = blockIdx.x;              // 0..127
    int l = blockIdx.y;              // 0..3
    int k = threadIdx.x * 4;         // 0..508
    const float inv_nf = 1.0f / (float)NFF;
    float4 accc[BB], accs[BB];
    #pragma unroll
    for (int b = 0; b < BB; b++) {
        accc[b] = make_float4(0.f,0.f,0.f,0.f);
        accs[b] = make_float4(0.f,0.f,0.f,0.f);
    }
    const float* wcp = wc + (((size_t)l*CC)*CC + o)*KK + k;
    const float* wsp = ws + (((size_t)l*CC)*CC + o)*KK + k;
    #pragma unroll 2
    for (int i = 0; i < CC; i++) {
        float4 wcv = *(const float4*)(wcp + (size_t)i*CC*KK);
        float4 wsv = *(const float4*)(wsp + (size_t)i*CC*KK);
        #pragma unroll
        for (int b = 0; b < BB; b++) {
            float4 xc = *(const float4*)(g_xch + ((size_t)b*CC + i)*KK + k);
            float4 xs = *(const float4*)(g_xsp + ((size_t)b*CC + i)*KK + k);
            accc[b].x += xc.x*wcv.x + xs.x*wsv.x;
            accc[b].y += xc.y*wcv.y + xs.y*wsv.y;
            accc[b].z += xc.z*wcv.z + xs.z*wsv.z;
            accc[b].w += xc.w*wcv.w + xs.w*wsv.w;
            accs[b].x += xc.x*wsv.x - xs.x*wcv.x;
            accs[b].y += xc.y*wsv.y - xs.y*wcv.y;
            accs[b].z += xc.z*wsv.z - xs.z*wcv.z;
            accs[b].w += xc.w*wsv.w - xs.w*wcv.w;
        }
    }
    #pragma unroll
    for (int b = 0; b < BB; b++) {
        size_t o4 = ((size_t)b*CC + o)*KK + k;
        bf162* fa = reinterpret_cast<bf162*>(&g_fAb[l][o4]);
        bf162* fb = reinterpret_cast<bf162*>(&g_fBb[l][o4]);
        fa[0] = __floats2bfloat162_rn( 2.0f*inv_nf*accc[b].x,  2.0f*inv_nf*accc[b].y);
        fa[1] = __floats2bfloat162_rn( 2.0f*inv_nf*accc[b].z,  2.0f*inv_nf*accc[b].w);
        fb[0] = __floats2bfloat162_rn(-2.0f*inv_nf*accs[b].x, -2.0f*inv_nf*accs[b].y);
        fb[1] = __floats2bfloat162_rn(-2.0f*inv_nf*accs[b].z, -2.0f*inv_nf*accs[b].w);
    }
}

// -------- K4b: f0h, all layers --------
__global__ void k_f0h_all(const float* __restrict__ w0, const float* __restrict__ convb) {
    int l = blockIdx.x;
    int t = threadIdx.x;
    int b = t >> 7, o = t & 127;
    float acc = 0.f;
    #pragma unroll 4
    for (int i = 0; i < CC; i++)
        acc += g_x0h[b*CC + i] * __ldg(&w0[((size_t)l*CC + i)*CC + o]);
    g_f0h[l][t] = acc * (1.0f / (float)NFF) + convb[l*CC + o];
}

// -------- K5a: inverse spectral GEMM, bf16 TC, all layers batched --------
// x1[b,m,n] = sum_k fA[b,m,k]*Bc[k,n] + fB[b,m,k]*Bs[k,n]; B from transposed [n][k].
// block 64(m) x 128(n), k-chunk 32.
__global__ void k_inv_spec_all() {
    __shared__ bf16 As[2][64][40];
    __shared__ bf16 Bsm[2][128][40];
    int z  = blockIdx.z;
    int b  = z & (BB-1);
    int l  = z >> 2;
    int m0 = blockIdx.y * 64;
    int n0 = blockIdx.x * 128;
    int tid = threadIdx.x;
    int lane = tid & 31, wid = tid >> 5;
    int wm = wid >> 2, wn = wid & 3;
    int g = lane >> 2, tig = lane & 3;
    float acc[2][4][4] = {};   // [ms][ns][4]
    const bf16* fA = g_fAb[l] + ((size_t)b*CC + m0)*KK;
    const bf16* fB = g_fBb[l] + ((size_t)b*CC + m0)*KK;
    const bf16* BcT = g_BcT + ((size_t)b*NN + n0)*KK;
    const bf16* BsT = g_BsT + ((size_t)b*NN + n0)*KK;
    int arow = tid >> 2, ac8 = (tid & 3) * 8;
    for (int r0 = 0; r0 < KK; r0 += 32) {
        *(uint4*)&As[0][arow][ac8] = *(const uint4*)&fA[(size_t)arow*KK + r0 + ac8];
        *(uint4*)&As[1][arow][ac8] = *(const uint4*)&fB[(size_t)arow*KK + r0 + ac8];
        #pragma unroll
        for (int t = 0; t < 2; t++) {
            int brow = (tid >> 2) + t*64;
            *(uint4*)&Bsm[0][brow][ac8] = *(const uint4*)&BcT[(size_t)brow*KK + r0 + ac8];
            *(uint4*)&Bsm[1][brow][ac8] = *(const uint4*)&BsT[(size_t)brow*KK + r0 + ac8];
        }
        __syncthreads();
        #pragma unroll
        for (int kk = 0; kk < 32; kk += 16) {
            #pragma unroll
            for (int p = 0; p < 2; p++) {
                uint32_t af[2][4];
                #pragma unroll
                for (int ms = 0; ms < 2; ms++) {
                    int m = wm*32 + ms*16;
                    af[ms][0] = *(const uint32_t*)&As[p][m+g  ][kk + 2*tig    ];
                    af[ms][1] = *(const uint32_t*)&As[p][m+g+8][kk + 2*tig    ];
                    af[ms][2] = *(const uint32_t*)&As[p][m+g  ][kk + 2*tig + 8];
                    af[ms][3] = *(const uint32_t*)&As[p][m+g+8][kk + 2*tig + 8];
                }
                #pragma unroll
                for (int ns = 0; ns < 4; ns++) {
                    int n = wn*32 + ns*8;
                    uint32_t bf[2];
                    bf[0] = *(const uint32_t*)&Bsm[p][n+g][kk + 2*tig    ];
                    bf[1] = *(const uint32_t*)&Bsm[p][n+g][kk + 2*tig + 8];
                    #pragma unroll
                    for (int ms = 0; ms < 2; ms++)
                        mma_bf16(acc[ms][ns], af[ms], bf);
                }
            }
        }
        __syncthreads();
    }
    float* X1 = g_x1[l] + (size_t)b*CC*NN;
    #pragma unroll
    for (int ms = 0; ms < 2; ms++) {
        #pragma unroll
        for (int ns = 0; ns < 4; ns++) {
            int m = m0 + wm*32 + ms*16 + g;
            int n = n0 + wn*32 + ns*8 + tig*2;
            X1[(size_t)m*NN + n]         = acc[ms][ns][0];
            X1[(size_t)m*NN + n + 1]     = acc[ms][ns][1];
            X1[(size_t)(m+8)*NN + n]     = acc[ms][ns][2];
            X1[(size_t)(m+8)*NN + n + 1] = acc[ms][ns][3];
        }
    }
}

// -------- K5b: conv via 3xTF32 + epilogue --------
__global__ void k_conv_tc(const float* __restrict__ convw, int l, int cur) {
    __shared__ float Ah[64][20], Al[64][20];
    __shared__ float Bh[16][132], Bl[16][132];
    int b  = blockIdx.z;
    int m0 = blockIdx.y * 64;
    int n0 = blockIdx.x * 128;
    int tid = threadIdx.x;
    int lane = tid & 31, wid = tid >> 5;
    int wm = wid >> 2, wn = wid & 3;
    int g = lane >> 2, tig = lane & 3;
    float acc[2][4][4] = {};
    const float* W = convw + (size_t)l*CC*CC + (size_t)m0*CC;
    const float* H = g_h[cur] + (size_t)b*CC*NN;
    int arow = tid >> 2, ac4 = (tid & 3) * 4;
    for (int r0 = 0; r0 < CC; r0 += 16) {
        float4 va = *(const float4*)&W[(size_t)arow*CC + r0 + ac4];
        float h0,l0,h1,l1,h2,l2,h3,l3;
        split_tf32(va.x, h0, l0); split_tf32(va.y, h1, l1);
        split_tf32(va.z, h2, l2); split_tf32(va.w, h3, l3);
        Ah[arow][ac4] = h0; Ah[arow][ac4+1] = h1; Ah[arow][ac4+2] = h2; Ah[arow][ac4+3] = h3;
        Al[arow][ac4] = l0; Al[arow][ac4+1] = l1; Al[arow][ac4+2] = l2; Al[arow][ac4+3] = l3;
        #pragma unroll
        for (int t = 0; t < 2; t++) {
            int idx = tid + t*256;
            int brow = idx >> 5, bc4 = (idx & 31) * 4;
            float4 vb = *(const float4*)&H[(size_t)(r0+brow)*NN + n0 + bc4];
            float bh0,bl0,bh1,bl1,bh2,bl2,bh3,bl3;
            split_tf32(vb.x, bh0, bl0); split_tf32(vb.y, bh1, bl1);
            split_tf32(vb.z, bh2, bl2); split_tf32(vb.w, bh3, bl3);
            Bh[brow][bc4] = bh0; Bh[brow][bc4+1] = bh1; Bh[brow][bc4+2] = bh2; Bh[brow][bc4+3] = bh3;
            Bl[brow][bc4] = bl0; Bl[brow][bc4+1] = bl1; Bl[brow][bc4+2] = bl2; Bl[brow][bc4+3] = bl3;
        }
        __syncthreads();
        #pragma unroll
        for (int kk = 0; kk < 16; kk += 8) {
            uint32_t afh[2][4], afl[2][4];
            #pragma unroll
            for (int ms = 0; ms < 2; ms++) {
                int m = wm*32 + ms*16;
                afh[ms][0] = __float_as_uint(Ah[m+g  ][kk+tig  ]);
                afh[ms][1] = __float_as_uint(Ah[m+g+8][kk+tig  ]);
                afh[ms][2] = __float_as_uint(Ah[m+g  ][kk+tig+4]);
                afh[ms][3] = __float_as_uint(Ah[m+g+8][kk+tig+4]);
                afl[ms][0] = __float_as_uint(Al[m+g  ][kk+tig  ]);
                afl[ms][1] = __float_as_uint(Al[m+g+8][kk+tig  ]);
                afl[ms][2] = __float_as_uint(Al[m+g  ][kk+tig+4]);
                afl[ms][3] = __float_as_uint(Al[m+g+8][kk+tig+4]);
            }
            #pragma unroll
            for (int ns = 0; ns < 4; ns++) {
                int n = wn*32 + ns*8;
                uint32_t bfh[2], bfl[2];
                bfh[0] = __float_as_uint(Bh[kk+tig  ][n+g]);
                bfh[1] = __float_as_uint(Bh[kk+tig+4][n+g]);
                bfl[0] = __float_as_uint(Bl[kk+tig  ][n+g]);
                bfl[1] = __float_as_uint(Bl[kk+tig+4][n+g]);
                #pragma unroll
                for (int ms = 0; ms < 2; ms++) {
                    mma_tf32(acc[ms][ns], afh[ms], bfh);
                    mma_tf32(acc[ms][ns], afh[ms], bfl);
                    mma_tf32(acc[ms][ns], afl[ms], bfh);
                }
            }
        }
        __syncthreads();
    }
    int nxt = cur ^ 1;
    const float* X1 = g_x1[l] + (size_t)b*CC*NN;
    float* Hn = g_h[nxt] + (size_t)b*CC*NN;
    #pragma unroll
    for (int ms = 0; ms < 2; ms++) {
        #pragma unroll
        for (int ns = 0; ns < 4; ns++) {
            int m = m0 + wm*32 + ms*16 + g;
            int n = n0 + wn*32 + ns*8 + tig*2;
            float bias0 = g_f0h[l][b*CC + m];
            float bias1 = g_f0h[l][b*CC + m + 8];
            float v0 = acc[ms][ns][0] + bias0 + X1[(size_t)m*NN + n];
            float v1 = acc[ms][ns][1] + bias0 + X1[(size_t)m*NN + n + 1];
            float v2 = acc[ms][ns][2] + bias1 + X1[(size_t)(m+8)*NN + n];
            float v3 = acc[ms][ns][3] + bias1 + X1[(size_t)(m+8)*NN + n + 1];
            if (l < LL - 1) {
                v0 = gelu_exact(v0); v1 = gelu_exact(v1);
                v2 = gelu_exact(v2); v3 = gelu_exact(v3);
            }
            Hn[(size_t)m*NN + n]         = v0;
            Hn[(size_t)m*NN + n + 1]     = v1;
            Hn[(size_t)(m+8)*NN + n]     = v2;
            Hn[(size_t)(m+8)*NN + n + 1] = v3;
        }
    }
}

// -------- K6: head --------
__global__ void k_head(const float* __restrict__ w1, const float* __restrict__ b1,
                       const float* __restrict__ w2, const float* __restrict__ b2,
                       float* __restrict__ out, int cur) {
    __shared__ float sh[CC][32];
    __shared__ float red[CC][33];
    int b  = blockIdx.y;
    int n0 = blockIdx.x * 32;
    int f = threadIdx.x;
    const float* H = g_h[cur] + (size_t)b*CC*NN + n0;
    #pragma unroll 4
    for (int c4 = 0; c4 < CC; c4 += 4) {
        int row = c4 + (f >> 5);
        int col = f & 31;
        sh[row][col] = H[(size_t)row*NN + col];
    }
    __syncthreads();
    float acc[32];
    float bv = b1[f];
    #pragma unroll
    for (int j = 0; j < 32; j++) acc[j] = bv;
    for (int c = 0; c < CC; c++) {
        float w = __ldg(&w1[(size_t)c*FCD + f]);
        #pragma unroll
        for (int j = 0; j < 32; j++) acc[j] += sh[c][j] * w;
    }
    float w2f = __ldg(&w2[f]);
    #pragma unroll
    for (int j = 0; j < 32; j++)
        red[f][j] = gelu_exact(acc[j]) * w2f;
    __syncthreads();
    if (f < 32) {
        float s = b2[0];
        #pragma unroll 8
        for (int q = 0; q < CC; q++) s += red[q][f];
        out[(size_t)b*NN + n0 + f] = s;
    }
}

// -------- launch --------
extern "C" void kernel_launch(void* const* d_in, const int* in_sizes, int n_in,
                              void* d_out, int out_size) {
    (void)in_sizes; (void)n_in; (void)out_size;
    const float* x     = (const float*)d_in[0];
    const float* xf    = (const float*)d_in[1];
    const int*   ind   = (const int*)  d_in[2];
    const float* modes = (const float*)d_in[3];
    const float* fc0_w = (const float*)d_in[4];
    const float* fc0_b = (const float*)d_in[5];
    const float* wc    = (const float*)d_in[6];
    const float* ws    = (const float*)d_in[7];
    const float* w0    = (const float*)d_in[8];
    const float* convw = (const float*)d_in[9];
    const float* convb = (const float*)d_in[10];
    const float* fc1_w = (const float*)d_in[11];
    const float* fc1_b = (const float*)d_in[12];
    const float* fc2_w = (const float*)d_in[13];
    const float* fc2_b = (const float*)d_in[14];
    float* out = (float*)d_out;

    k_basis<<<(BB*KK*NN + 255)/256, 256>>>(xf, ind, modes);
    dim3 gt(NN/32, KK/32, BB);
    k_bT<<<gt, dim3(32,8)>>>();

    dim3 g2(NN/256, CC, BB);
    k_fc0<<<g2, 256>>>(x, fc0_w, fc0_b);

    k_x0h<<<BB*CC, 256>>>();
    dim3 g3(KK/64, CC/32, BB*FWD_S);
    k_fwd_tc<<<g3, 256>>>();
    k_fwd_red<<<BB*CC*KK/1024, 256>>>();

    dim3 g4(CC, LL);
    k_mix_all<<<g4, 128>>>(wc, ws);
    k_f0h_all<<<LL, BB*CC>>>(w0, convb);
    dim3 g5(NN/128, CC/64, BB*LL);
    k_inv_spec_all<<<g5, 256>>>();

    int cur = 0;
    for (int l = 0; l < LL; l++) {
        dim3 g6(NN/128, CC/64, BB);
        k_conv_tc<<<g6, 256>>>(convw, l, cur);
        cur ^= 1;
    }

    dim3 g7(NN/32, BB);
    k_head<<<g7, 128>>>(fc1_w, fc1_b, fc2_w, fc2_b, out, cur);
}

// round 8
// speedup vs baseline: 1.2084x; 1.0163x over previous
#include <cuda_runtime.h>
#include <cuda_bf16.h>
#include <math.h>
#include <stdint.h>

#define BB 4
#define NN 4096
#define NFF 8192
#define KK 512
#define CC 128
#define LL 4
#define INDIM 3
#define FCD 128
#define FWD_S 2

typedef __nv_bfloat16 bf16;
typedef __nv_bfloat162 bf162;

// -------- scratch --------
__device__ bf16  g_Bc [BB*KK*NN];      // basis [b][k][n]
__device__ bf16  g_Bs [BB*KK*NN];
__device__ bf16  g_BcT[BB*NN*KK];      // basis [b][n][k]
__device__ bf16  g_BsT[BB*NN*KK];
__device__ float g_wqn[BB*NN];
__device__ float g_h[2][BB*CC*NN];
__device__ bf16  g_hwb[BB*CC*NN];      // h0*wqn bf16
__device__ float g_xch[BB*CC*KK];
__device__ float g_xsp[BB*CC*KK];
__device__ float g_pc[FWD_S][BB*CC*KK];
__device__ float g_ps[FWD_S][BB*CC*KK];
__device__ bf16  g_fAb[LL][BB*CC*KK];
__device__ bf16  g_fBb[LL][BB*CC*KK];
__device__ bf16  g_x1b[LL][BB*CC*NN];  // spectral inverse, bf16
__device__ float g_x0h[BB*CC];
__device__ float g_f0h[LL][BB*CC];

__device__ __forceinline__ float gelu_exact(float v) {
    return 0.5f * v * (1.0f + erff(v * 0.7071067811865476f));
}
__device__ __forceinline__ float tf32r(float x) {
    float r;
    asm("cvt.rna.tf32.f32 %0, %1;" : "=f"(r) : "f"(x));
    return r;
}
__device__ __forceinline__ void split_tf32(float v, float& hi, float& lo) {
    hi = tf32r(v);
    lo = tf32r(v - hi);
}
__device__ __forceinline__ void mma_tf32(float (&d)[4], const uint32_t (&a)[4],
                                         const uint32_t (&b)[2]) {
    asm volatile(
        "mma.sync.aligned.m16n8k8.row.col.f32.tf32.tf32.f32 "
        "{%0,%1,%2,%3}, {%4,%5,%6,%7}, {%8,%9}, {%0,%1,%2,%3};"
        : "+f"(d[0]), "+f"(d[1]), "+f"(d[2]), "+f"(d[3])
        : "r"(a[0]), "r"(a[1]), "r"(a[2]), "r"(a[3]), "r"(b[0]), "r"(b[1]));
}
__device__ __forceinline__ void mma_bf16(float (&d)[4], const uint32_t (&a)[4],
                                         const uint32_t (&b)[2]) {
    asm volatile(
        "mma.sync.aligned.m16n8k16.row.col.f32.bf16.bf16.f32 "
        "{%0,%1,%2,%3}, {%4,%5,%6,%7}, {%8,%9}, {%0,%1,%2,%3};"
        : "+f"(d[0]), "+f"(d[1]), "+f"(d[2]), "+f"(d[3])
        : "r"(a[0]), "r"(a[1]), "r"(a[2]), "r"(a[3]), "r"(b[0]), "r"(b[1]));
}

// -------- K0: wqn --------
__global__ void k_wqn(const float* __restrict__ xf, const int* __restrict__ ind) {
    int idx = blockIdx.x * 256 + threadIdx.x;   // b*NN + n
    int n = idx & (NN - 1);
    int b = idx >> 12;
    int f = __ldg(&ind[n]);
    g_wqn[idx] = __ldg(&xf[((size_t)b*NFF + f)*4 + 2]) * (float)NN;
}

// -------- K1: basis precompute, writes BOTH layouts (fused transpose) --------
__global__ void k_basis(const float* __restrict__ xf, const int* __restrict__ ind,
                        const float* __restrict__ modes) {
    __shared__ bf16 tc[32][33];
    __shared__ bf16 ts[32][33];
    int b  = blockIdx.z;
    int k0 = blockIdx.y * 32;
    int n0 = blockIdx.x * 32;
    int tx = threadIdx.x & 31;        // n
    int ty = threadIdx.x >> 5;        // 0..7
    int n = n0 + tx;
    int f = __ldg(&ind[n]);
    const float* xfp = xf + ((size_t)b * NFF + f) * 4;
    float gx = __ldg(&xfp[0]);
    float gy = __ldg(&xfp[1]);
    #pragma unroll
    for (int j = 0; j < 4; j++) {
        int kr = ty*4 + j;
        float mx = __ldg(&modes[2*(k0+kr)]);
        float my = __ldg(&modes[2*(k0+kr)+1]);
        float s, c;
        __sincosf(gx*mx + gy*my, &s, &c);
        tc[kr][tx] = __float2bfloat16(c);
        ts[kr][tx] = __float2bfloat16(s);
    }
    __syncthreads();
    // write [k][n]
    bf16* dc = g_Bc + ((size_t)b*KK + k0)*NN + n0;
    bf16* ds = g_Bs + ((size_t)b*KK + k0)*NN + n0;
    #pragma unroll
    for (int j = 0; j < 4; j++) {
        int kr = ty*4 + j;
        dc[(size_t)kr*NN + tx] = tc[kr][tx];
        ds[(size_t)kr*NN + tx] = ts[kr][tx];
    }
    // write [n][k] (transposed read from smem)
    bf16* dct = g_BcT + ((size_t)b*NN + n0)*KK + k0;
    bf16* dst = g_BsT + ((size_t)b*NN + n0)*KK + k0;
    #pragma unroll
    for (int j = 0; j < 4; j++) {
        int nr = ty*4 + j;
        dct[(size_t)nr*KK + tx] = tc[tx][nr];
        dst[(size_t)nr*KK + tx] = ts[tx][nr];
    }
}

// -------- K2: fc0 --------
__global__ void k_fc0(const float* __restrict__ x, const float* __restrict__ w,
                      const float* __restrict__ bias) {
    int n = blockIdx.x * blockDim.x + threadIdx.x;
    int c = blockIdx.y;
    int b = blockIdx.z;
    const float* xp = x + ((size_t)b * NN + n) * INDIM;
    float acc = bias[c]
              + xp[0] * w[0*CC + c]
              + xp[1] * w[1*CC + c]
              + xp[2] * w[2*CC + c];
    size_t o = ((size_t)b*CC + c) * NN + n;
    g_h[0][o] = acc;
    g_hwb[o]  = __float2bfloat16(acc * g_wqn[b*NN + n]);
}

// -------- K2b: x0h (bf16 source) --------
__global__ void k_x0h() {
    int bc = blockIdx.x;
    const bf162* p = reinterpret_cast<const bf162*>(g_hwb + (size_t)bc * NN);
    float acc = 0.f;
    for (int n = threadIdx.x; n < NN/2; n += 256) {
        float2 v = __bfloat1622float2(p[n]);
        acc += v.x + v.y;
    }
    __shared__ float red[256];
    red[threadIdx.x] = acc;
    __syncthreads();
    for (int s = 128; s > 0; s >>= 1) {
        if (threadIdx.x < s) red[threadIdx.x] += red[threadIdx.x + s];
        __syncthreads();
    }
    if (threadIdx.x == 0) g_x0h[bc] = red[0];
}

// -------- K3: forward dual GEMM, bf16 TC, split-N (FWD_S=2) --------
__global__ void k_fwd_tc() {
    __shared__ bf16 As[32][72];
    __shared__ bf16 Bsm[2][64][72];
    int z   = blockIdx.z;
    int b   = z >> 1;
    int s   = z & 1;
    int m0  = blockIdx.y * 32;
    int ko0 = blockIdx.x * 64;
    int tid = threadIdx.x;
    int lane = tid & 31, wid = tid >> 5;
    int wm = wid >> 2, wn = wid & 3;
    int g = lane >> 2, tig = lane & 3;
    float acc[2][2][4] = {};
    const bf16* A  = g_hwb + ((size_t)b*CC + m0) * NN + s * (NN/FWD_S);
    const bf16* Bc = g_Bc  + ((size_t)b*KK + ko0) * NN + s * (NN/FWD_S);
    const bf16* Bs = g_Bs  + ((size_t)b*KK + ko0) * NN + s * (NN/FWD_S);
    int arow = tid >> 3, ac8 = (tid & 7) * 8;
    for (int r0 = 0; r0 < NN/FWD_S; r0 += 64) {
        *(uint4*)&As[arow][ac8] = *(const uint4*)&A[(size_t)arow*NN + r0 + ac8];
        #pragma unroll
        for (int t = 0; t < 2; t++) {
            int brow = (tid >> 3) + t*32;
            *(uint4*)&Bsm[0][brow][ac8] = *(const uint4*)&Bc[(size_t)brow*NN + r0 + ac8];
            *(uint4*)&Bsm[1][brow][ac8] = *(const uint4*)&Bs[(size_t)brow*NN + r0 + ac8];
        }
        __syncthreads();
        #pragma unroll
        for (int kk = 0; kk < 64; kk += 16) {
            uint32_t af[4];
            int m = wm * 16;
            af[0] = *(const uint32_t*)&As[m+g  ][kk + 2*tig    ];
            af[1] = *(const uint32_t*)&As[m+g+8][kk + 2*tig    ];
            af[2] = *(const uint32_t*)&As[m+g  ][kk + 2*tig + 8];
            af[3] = *(const uint32_t*)&As[m+g+8][kk + 2*tig + 8];
            #pragma unroll
            for (int p = 0; p < 2; p++) {
                #pragma unroll
                for (int ns = 0; ns < 2; ns++) {
                    int n = wn * 16 + ns * 8;
                    uint32_t bf[2];
                    bf[0] = *(const uint32_t*)&Bsm[p][n+g][kk + 2*tig    ];
                    bf[1] = *(const uint32_t*)&Bsm[p][n+g][kk + 2*tig + 8];
                    mma_bf16(acc[p][ns], af, bf);
                }
            }
        }
        __syncthreads();
    }
    #pragma unroll
    for (int ns = 0; ns < 2; ns++) {
        int m = m0 + wm*16 + g;
        int k = ko0 + wn*16 + ns*8 + tig*2;
        size_t o0 = ((size_t)b*CC + m)*KK + k;
        size_t o1 = ((size_t)b*CC + m + 8)*KK + k;
        g_pc[s][o0]   = acc[0][ns][0];
        g_pc[s][o0+1] = acc[0][ns][1];
        g_pc[s][o1]   = acc[0][ns][2];
        g_pc[s][o1+1] = acc[0][ns][3];
        g_ps[s][o0]   = acc[1][ns][0];
        g_ps[s][o0+1] = acc[1][ns][1];
        g_ps[s][o1]   = acc[1][ns][2];
        g_ps[s][o1+1] = acc[1][ns][3];
    }
}

__global__ void k_fwd_red() {
    int i = (blockIdx.x * 256 + threadIdx.x) * 4;
    float4 c0 = *(const float4*)&g_pc[0][i];
    float4 c1 = *(const float4*)&g_pc[1][i];
    float4 s0 = *(const float4*)&g_ps[0][i];
    float4 s1 = *(const float4*)&g_ps[1][i];
    float4 c, s;
    c.x = c0.x+c1.x; c.y = c0.y+c1.y; c.z = c0.z+c1.z; c.w = c0.w+c1.w;
    s.x = s0.x+s1.x; s.y = s0.y+s1.y; s.z = s0.z+s1.z; s.w = s0.w+s1.w;
    *(float4*)&g_xch[i] = c;
    *(float4*)&g_xsp[i] = s;
}

// -------- K4: mode mix, all layers, float4 over k, i-unroll 4 --------
__global__ void k_mix_all(const float* __restrict__ wc, const float* __restrict__ ws) {
    int o = blockIdx.x;
    int l = blockIdx.y;
    int k = threadIdx.x * 4;
    const float inv_nf = 1.0f / (float)NFF;
    float4 accc[BB], accs[BB];
    #pragma unroll
    for (int b = 0; b < BB; b++) {
        accc[b] = make_float4(0.f,0.f,0.f,0.f);
        accs[b] = make_float4(0.f,0.f,0.f,0.f);
    }
    const float* wcp = wc + (((size_t)l*CC)*CC + o)*KK + k;
    const float* wsp = ws + (((size_t)l*CC)*CC + o)*KK + k;
    #pragma unroll 4
    for (int i = 0; i < CC; i++) {
        float4 wcv = *(const float4*)(wcp + (size_t)i*CC*KK);
        float4 wsv = *(const float4*)(wsp + (size_t)i*CC*KK);
        #pragma unroll
        for (int b = 0; b < BB; b++) {
            float4 xc = *(const float4*)(g_xch + ((size_t)b*CC + i)*KK + k);
            float4 xs = *(const float4*)(g_xsp + ((size_t)b*CC + i)*KK + k);
            accc[b].x += xc.x*wcv.x + xs.x*wsv.x;
            accc[b].y += xc.y*wcv.y + xs.y*wsv.y;
            accc[b].z += xc.z*wcv.z + xs.z*wsv.z;
            accc[b].w += xc.w*wcv.w + xs.w*wsv.w;
            accs[b].x += xc.x*wsv.x - xs.x*wcv.x;
            accs[b].y += xc.y*wsv.y - xs.y*wcv.y;
            accs[b].z += xc.z*wsv.z - xs.z*wcv.z;
            accs[b].w += xc.w*wsv.w - xs.w*wcv.w;
        }
    }
    #pragma unroll
    for (int b = 0; b < BB; b++) {
        size_t o4 = ((size_t)b*CC + o)*KK + k;
        bf162* fa = reinterpret_cast<bf162*>(&g_fAb[l][o4]);
        bf162* fb = reinterpret_cast<bf162*>(&g_fBb[l][o4]);
        fa[0] = __floats2bfloat162_rn( 2.0f*inv_nf*accc[b].x,  2.0f*inv_nf*accc[b].y);
        fa[1] = __floats2bfloat162_rn( 2.0f*inv_nf*accc[b].z,  2.0f*inv_nf*accc[b].w);
        fb[0] = __floats2bfloat162_rn(-2.0f*inv_nf*accs[b].x, -2.0f*inv_nf*accs[b].y);
        fb[1] = __floats2bfloat162_rn(-2.0f*inv_nf*accs[b].z, -2.0f*inv_nf*accs[b].w);
    }
}

// -------- K4b: f0h --------
__global__ void k_f0h_all(const float* __restrict__ w0, const float* __restrict__ convb) {
    int l = blockIdx.x;
    int t = threadIdx.x;
    int b = t >> 7, o = t & 127;
    float acc = 0.f;
    #pragma unroll 4
    for (int i = 0; i < CC; i++)
        acc += g_x0h[b*CC + i] * __ldg(&w0[((size_t)l*CC + i)*CC + o]);
    g_f0h[l][t] = acc * (1.0f / (float)NFF) + convb[l*CC + o];
}

// -------- K5a: inverse spectral GEMM, bf16 TC, bf16 x1 out --------
__global__ void k_inv_spec_all() {
    __shared__ bf16 As[2][64][40];
    __shared__ bf16 Bsm[2][128][40];
    int z  = blockIdx.z;
    int b  = z & (BB-1);
    int l  = z >> 2;
    int m0 = blockIdx.y * 64;
    int n0 = blockIdx.x * 128;
    int tid = threadIdx.x;
    int lane = tid & 31, wid = tid >> 5;
    int wm = wid >> 2, wn = wid & 3;
    int g = lane >> 2, tig = lane & 3;
    float acc[2][4][4] = {};
    const bf16* fA = g_fAb[l] + ((size_t)b*CC + m0)*KK;
    const bf16* fB = g_fBb[l] + ((size_t)b*CC + m0)*KK;
    const bf16* BcT = g_BcT + ((size_t)b*NN + n0)*KK;
    const bf16* BsT = g_BsT + ((size_t)b*NN + n0)*KK;
    int arow = tid >> 2, ac8 = (tid & 3) * 8;
    for (int r0 = 0; r0 < KK; r0 += 32) {
        *(uint4*)&As[0][arow][ac8] = *(const uint4*)&fA[(size_t)arow*KK + r0 + ac8];
        *(uint4*)&As[1][arow][ac8] = *(const uint4*)&fB[(size_t)arow*KK + r0 + ac8];
        #pragma unroll
        for (int t = 0; t < 2; t++) {
            int brow = (tid >> 2) + t*64;
            *(uint4*)&Bsm[0][brow][ac8] = *(const uint4*)&BcT[(size_t)brow*KK + r0 + ac8];
            *(uint4*)&Bsm[1][brow][ac8] = *(const uint4*)&BsT[(size_t)brow*KK + r0 + ac8];
        }
        __syncthreads();
        #pragma unroll
        for (int kk = 0; kk < 32; kk += 16) {
            #pragma unroll
            for (int p = 0; p < 2; p++) {
                uint32_t af[2][4];
                #pragma unroll
                for (int ms = 0; ms < 2; ms++) {
                    int m = wm*32 + ms*16;
                    af[ms][0] = *(const uint32_t*)&As[p][m+g  ][kk + 2*tig    ];
                    af[ms][1] = *(const uint32_t*)&As[p][m+g+8][kk + 2*tig    ];
                    af[ms][2] = *(const uint32_t*)&As[p][m+g  ][kk + 2*tig + 8];
                    af[ms][3] = *(const uint32_t*)&As[p][m+g+8][kk + 2*tig + 8];
                }
                #pragma unroll
                for (int ns = 0; ns < 4; ns++) {
                    int n = wn*32 + ns*8;
                    uint32_t bf[2];
                    bf[0] = *(const uint32_t*)&Bsm[p][n+g][kk + 2*tig    ];
                    bf[1] = *(const uint32_t*)&Bsm[p][n+g][kk + 2*tig + 8];
                    #pragma unroll
                    for (int ms = 0; ms < 2; ms++)
                        mma_bf16(acc[ms][ns], af[ms], bf);
                }
            }
        }
        __syncthreads();
    }
    bf16* X1 = g_x1b[l] + (size_t)b*CC*NN;
    #pragma unroll
    for (int ms = 0; ms < 2; ms++) {
        #pragma unroll
        for (int ns = 0; ns < 4; ns++) {
            int m = m0 + wm*32 + ms*16 + g;
            int n = n0 + wn*32 + ns*8 + tig*2;
            *reinterpret_cast<bf162*>(&X1[(size_t)m*NN + n]) =
                __floats2bfloat162_rn(acc[ms][ns][0], acc[ms][ns][1]);
            *reinterpret_cast<bf162*>(&X1[(size_t)(m+8)*NN + n]) =
                __floats2bfloat162_rn(acc[ms][ns][2], acc[ms][ns][3]);
        }
    }
}

// -------- K5b: conv via 3xTF32 + epilogue (x1 bf16 reads) --------
__global__ void k_conv_tc(const float* __restrict__ convw, int l, int cur) {
    __shared__ float Ah[64][20], Al[64][20];
    __shared__ float Bh[16][132], Bl[16][132];
    int b  = blockIdx.z;
    int m0 = blockIdx.y * 64;
    int n0 = blockIdx.x * 128;
    int tid = threadIdx.x;
    int lane = tid & 31, wid = tid >> 5;
    int wm = wid >> 2, wn = wid & 3;
    int g = lane >> 2, tig = lane & 3;
    float acc[2][4][4] = {};
    const float* W = convw + (size_t)l*CC*CC + (size_t)m0*CC;
    const float* H = g_h[cur] + (size_t)b*CC*NN;
    int arow = tid >> 2, ac4 = (tid & 3) * 4;
    for (int r0 = 0; r0 < CC; r0 += 16) {
        float4 va = *(const float4*)&W[(size_t)arow*CC + r0 + ac4];
        float h0,l0,h1,l1,h2,l2,h3,l3;
        split_tf32(va.x, h0, l0); split_tf32(va.y, h1, l1);
        split_tf32(va.z, h2, l2); split_tf32(va.w, h3, l3);
        Ah[arow][ac4] = h0; Ah[arow][ac4+1] = h1; Ah[arow][ac4+2] = h2; Ah[arow][ac4+3] = h3;
        Al[arow][ac4] = l0; Al[arow][ac4+1] = l1; Al[arow][ac4+2] = l2; Al[arow][ac4+3] = l3;
        #pragma unroll
        for (int t = 0; t < 2; t++) {
            int idx = tid + t*256;
            int brow = idx >> 5, bc4 = (idx & 31) * 4;
            float4 vb = *(const float4*)&H[(size_t)(r0+brow)*NN + n0 + bc4];
            float bh0,bl0,bh1,bl1,bh2,bl2,bh3,bl3;
            split_tf32(vb.x, bh0, bl0); split_tf32(vb.y, bh1, bl1);
            split_tf32(vb.z, bh2, bl2); split_tf32(vb.w, bh3, bl3);
            Bh[brow][bc4] = bh0; Bh[brow][bc4+1] = bh1; Bh[brow][bc4+2] = bh2; Bh[brow][bc4+3] = bh3;
            Bl[brow][bc4] = bl0; Bl[brow][bc4+1] = bl1; Bl[brow][bc4+2] = bl2; Bl[brow][bc4+3] = bl3;
        }
        __syncthreads();
        #pragma unroll
        for (int kk = 0; kk < 16; kk += 8) {
            uint32_t afh[2][4], afl[2][4];
            #pragma unroll
            for (int ms = 0; ms < 2; ms++) {
                int m = wm*32 + ms*16;
                afh[ms][0] = __float_as_uint(Ah[m+g  ][kk+tig  ]);
                afh[ms][1] = __float_as_uint(Ah[m+g+8][kk+tig  ]);
                afh[ms][2] = __float_as_uint(Ah[m+g  ][kk+tig+4]);
                afh[ms][3] = __float_as_uint(Ah[m+g+8][kk+tig+4]);
                afl[ms][0] = __float_as_uint(Al[m+g  ][kk+tig  ]);
                afl[ms][1] = __float_as_uint(Al[m+g+8][kk+tig  ]);
                afl[ms][2] = __float_as_uint(Al[m+g  ][kk+tig+4]);
                afl[ms][3] = __float_as_uint(Al[m+g+8][kk+tig+4]);
            }
            #pragma unroll
            for (int ns = 0; ns < 4; ns++) {
                int n = wn*32 + ns*8;
                uint32_t bfh[2], bfl[2];
                bfh[0] = __float_as_uint(Bh[kk+tig  ][n+g]);
                bfh[1] = __float_as_uint(Bh[kk+tig+4][n+g]);
                bfl[0] = __float_as_uint(Bl[kk+tig  ][n+g]);
                bfl[1] = __float_as_uint(Bl[kk+tig+4][n+g]);
                #pragma unroll
                for (int ms = 0; ms < 2; ms++) {
                    mma_tf32(acc[ms][ns], afh[ms], bfh);
                    mma_tf32(acc[ms][ns], afh[ms], bfl);
                    mma_tf32(acc[ms][ns], afl[ms], bfh);
                }
            }
        }
        __syncthreads();
    }
    int nxt = cur ^ 1;
    const bf16* X1 = g_x1b[l] + (size_t)b*CC*NN;
    float* Hn = g_h[nxt] + (size_t)b*CC*NN;
    #pragma unroll
    for (int ms = 0; ms < 2; ms++) {
        #pragma unroll
        for (int ns = 0; ns < 4; ns++) {
            int m = m0 + wm*32 + ms*16 + g;
            int n = n0 + wn*32 + ns*8 + tig*2;
            float bias0 = g_f0h[l][b*CC + m];
            float bias1 = g_f0h[l][b*CC + m + 8];
            float2 x1a = __bfloat1622float2(*reinterpret_cast<const bf162*>(&X1[(size_t)m*NN + n]));
            float2 x1b = __bfloat1622float2(*reinterpret_cast<const bf162*>(&X1[(size_t)(m+8)*NN + n]));
            float v0 = acc[ms][ns][0] + bias0 + x1a.x;
            float v1 = acc[ms][ns][1] + bias0 + x1a.y;
            float v2 = acc[ms][ns][2] + bias1 + x1b.x;
            float v3 = acc[ms][ns][3] + bias1 + x1b.y;
            if (l < LL - 1) {
                v0 = gelu_exact(v0); v1 = gelu_exact(v1);
                v2 = gelu_exact(v2); v3 = gelu_exact(v3);
            }
            Hn[(size_t)m*NN + n]         = v0;
            Hn[(size_t)m*NN + n + 1]     = v1;
            Hn[(size_t)(m+8)*NN + n]     = v2;
            Hn[(size_t)(m+8)*NN + n + 1] = v3;
        }
    }
}

// -------- K6: head --------
__global__ void k_head(const float* __restrict__ w1, const float* __restrict__ b1,
                       const float* __restrict__ w2, const float* __restrict__ b2,
                       float* __restrict__ out, int cur) {
    __shared__ float sh[CC][32];
    __shared__ float red[CC][33];
    int b  = blockIdx.y;
    int n0 = blockIdx.x * 32;
    int f = threadIdx.x;
    const float* H = g_h[cur] + (size_t)b*CC*NN + n0;
    #pragma unroll 4
    for (int c4 = 0; c4 < CC; c4 += 4) {
        int row = c4 + (f >> 5);
        int col = f & 31;
        sh[row][col] = H[(size_t)row*NN + col];
    }
    __syncthreads();
    float acc[32];
    float bv = b1[f];
    #pragma unroll
    for (int j = 0; j < 32; j++) acc[j] = bv;
    for (int c = 0; c < CC; c++) {
        float w = __ldg(&w1[(size_t)c*FCD + f]);
        #pragma unroll
        for (int j = 0; j < 32; j++) acc[j] += sh[c][j] * w;
    }
    float w2f = __ldg(&w2[f]);
    #pragma unroll
    for (int j = 0; j < 32; j++)
        red[f][j] = gelu_exact(acc[j]) * w2f;
    __syncthreads();
    if (f < 32) {
        float s = b2[0];
        #pragma unroll 8
        for (int q = 0; q < CC; q++) s += red[q][f];
        out[(size_t)b*NN + n0 + f] = s;
    }
}

// -------- launch --------
extern "C" void kernel_launch(void* const* d_in, const int* in_sizes, int n_in,
                              void* d_out, int out_size) {
    (void)in_sizes; (void)n_in; (void)out_size;
    const float* x     = (const float*)d_in[0];
    const float* xf    = (const float*)d_in[1];
    const int*   ind   = (const int*)  d_in[2];
    const float* modes = (const float*)d_in[3];
    const float* fc0_w = (const float*)d_in[4];
    const float* fc0_b = (const float*)d_in[5];
    const float* wc    = (const float*)d_in[6];
    const float* ws    = (const float*)d_in[7];
    const float* w0    = (const float*)d_in[8];
    const float* convw = (const float*)d_in[9];
    const float* convb = (const float*)d_in[10];
    const float* fc1_w = (const float*)d_in[11];
    const float* fc1_b = (const float*)d_in[12];
    const float* fc2_w = (const float*)d_in[13];
    const float* fc2_b = (const float*)d_in[14];
    float* out = (float*)d_out;

    k_wqn<<<BB*NN/256, 256>>>(xf, ind);
    dim3 g1(NN/32, KK/32, BB);
    k_basis<<<g1, 256>>>(xf, ind, modes);

    dim3 g2(NN/256, CC, BB);
    k_fc0<<<g2, 256>>>(x, fc0_w, fc0_b);

    k_x0h<<<BB*CC, 256>>>();
    dim3 g3(KK/64, CC/32, BB*FWD_S);
    k_fwd_tc<<<g3, 256>>>();
    k_fwd_red<<<BB*CC*KK/1024, 256>>>();

    dim3 g4(CC, LL);
    k_mix_all<<<g4, 128>>>(wc, ws);
    k_f0h_all<<<LL, BB*CC>>>(w0, convb);
    dim3 g5(NN/128, CC/64, BB*LL);
    k_inv_spec_all<<<g5, 256>>>();

    int cur = 0;
    for (int l = 0; l < LL; l++) {
        dim3 g6(NN/128, CC/64, BB);
        k_conv_tc<<<g6, 256>>>(convw, l, cur);
        cur ^= 1;
    }

    dim3 g7(NN/32, BB);
    k_head<<<g7, 128>>>(fc1_w, fc1_b, fc2_w, fc2_b, out, cur);
}

// round 9
// speedup vs baseline: 1.2173x; 1.0074x over previous
#include <cuda_runtime.h>
#include <cuda_bf16.h>
#include <math.h>
#include <stdint.h>

#define BB 4
#define NN 4096
#define NFF 8192
#define KK 512
#define CC 128
#define LL 4
#define INDIM 3
#define FCD 128
#define FWD_S 2

typedef __nv_bfloat16 bf16;
typedef __nv_bfloat162 bf162;

// -------- scratch --------
__device__ bf16  g_Bc [BB*KK*NN];      // basis [b][k][n]
__device__ bf16  g_Bs [BB*KK*NN];
__device__ bf16  g_BcT[BB*NN*KK];      // basis [b][n][k]
__device__ bf16  g_BsT[BB*NN*KK];
__device__ float g_wqn[BB*NN];
__device__ float g_h[2][BB*CC*NN];
__device__ bf16  g_hwb[BB*CC*NN];      // h0*wqn bf16
__device__ float g_xch[BB*CC*KK];
__device__ float g_xsp[BB*CC*KK];
__device__ float g_pc[FWD_S][BB*CC*KK];
__device__ float g_ps[FWD_S][BB*CC*KK];
__device__ bf16  g_fAb[LL][BB*CC*KK];
__device__ bf16  g_fBb[LL][BB*CC*KK];
__device__ bf16  g_x1b[LL][BB*CC*NN];  // spectral inverse, bf16
__device__ float g_x0h[BB*CC];
__device__ float g_f0h[LL][BB*CC];

__device__ __forceinline__ float gelu_exact(float v) {
    return 0.5f * v * (1.0f + erff(v * 0.7071067811865476f));
}
__device__ __forceinline__ float tf32r(float x) {
    float r;
    asm("cvt.rna.tf32.f32 %0, %1;" : "=f"(r) : "f"(x));
    return r;
}
__device__ __forceinline__ void split_tf32(float v, float& hi, float& lo) {
    hi = tf32r(v);
    lo = tf32r(v - hi);
}
__device__ __forceinline__ void mma_tf32(float (&d)[4], const uint32_t (&a)[4],
                                         const uint32_t (&b)[2]) {
    asm volatile(
        "mma.sync.aligned.m16n8k8.row.col.f32.tf32.tf32.f32 "
        "{%0,%1,%2,%3}, {%4,%5,%6,%7}, {%8,%9}, {%0,%1,%2,%3};"
        : "+f"(d[0]), "+f"(d[1]), "+f"(d[2]), "+f"(d[3])
        : "r"(a[0]), "r"(a[1]), "r"(a[2]), "r"(a[3]), "r"(b[0]), "r"(b[1]));
}
__device__ __forceinline__ void mma_bf16(float (&d)[4], const uint32_t (&a)[4],
                                         const uint32_t (&b)[2]) {
    asm volatile(
        "mma.sync.aligned.m16n8k16.row.col.f32.bf16.bf16.f32 "
        "{%0,%1,%2,%3}, {%4,%5,%6,%7}, {%8,%9}, {%0,%1,%2,%3};"
        : "+f"(d[0]), "+f"(d[1]), "+f"(d[2]), "+f"(d[3])
        : "r"(a[0]), "r"(a[1]), "r"(a[2]), "r"(a[3]), "r"(b[0]), "r"(b[1]));
}

// -------- K0: wqn --------
__global__ void k_wqn(const float* __restrict__ xf, const int* __restrict__ ind) {
    int idx = blockIdx.x * 256 + threadIdx.x;
    int n = idx & (NN - 1);
    int b = idx >> 12;
    int f = __ldg(&ind[n]);
    g_wqn[idx] = __ldg(&xf[((size_t)b*NFF + f)*4 + 2]) * (float)NN;
}

// -------- K1: basis via integer-mode angle addition (MUFU-free hot path) --------
// modes[k] are integers in [-16,16]. Per (b,n): build cos/sin(j*gx), cos/sin(j*gy)
// tables for j=-16..16 from 2 precise sincosf seeds + angle-addition recurrence.
// Then each (k,n) is 4 smem loads + 6 fma.
__global__ void k_basis(const float* __restrict__ xf, const int* __restrict__ ind,
                        const float* __restrict__ modes) {
    __shared__ float txC[33][32], txS[33][32], tyC[33][32], tyS[33][32];
    __shared__ bf16 tc[32][34], ts[32][34];
    int b  = blockIdx.y;
    int n0 = blockIdx.x * 32;
    int tid = threadIdx.x;
    int tx = tid & 31;     // n lane
    int ty = tid >> 5;     // 0..7
    if (ty == 0) {
        int n = n0 + tx;
        int f = __ldg(&ind[n]);
        const float* xfp = xf + ((size_t)b*NFF + f)*4;
        float gx = __ldg(&xfp[0]);
        float gy = __ldg(&xfp[1]);
        float c1, s1;
        sincosf(gx, &s1, &c1);
        txC[16][tx] = 1.f; txS[16][tx] = 0.f;
        float cj = c1, sj = s1;
        #pragma unroll
        for (int j = 1; j <= 16; j++) {
            txC[16+j][tx] = cj;  txS[16+j][tx] = sj;
            txC[16-j][tx] = cj;  txS[16-j][tx] = -sj;
            float cn = cj*c1 - sj*s1;
            float sn = sj*c1 + cj*s1;
            cj = cn; sj = sn;
        }
        sincosf(gy, &s1, &c1);
        tyC[16][tx] = 1.f; tyS[16][tx] = 0.f;
        cj = c1; sj = s1;
        #pragma unroll
        for (int j = 1; j <= 16; j++) {
            tyC[16+j][tx] = cj;  tyS[16+j][tx] = sj;
            tyC[16-j][tx] = cj;  tyS[16-j][tx] = -sj;
            float cn = cj*c1 - sj*s1;
            float sn = sj*c1 + cj*s1;
            cj = cn; sj = sn;
        }
    }
    __syncthreads();
    for (int k0 = 0; k0 < KK; k0 += 32) {
        #pragma unroll
        for (int jj = 0; jj < 4; jj++) {
            int kr = ty*4 + jj;
            int k = k0 + kr;
            int jx = (int)__ldg(&modes[2*k])   + 16;
            int jy = (int)__ldg(&modes[2*k+1]) + 16;
            float ca = txC[jx][tx], sa = txS[jx][tx];
            float cb = tyC[jy][tx], sb = tyS[jy][tx];
            float c = ca*cb - sa*sb;
            float s = sa*cb + ca*sb;
            bf16 cb16 = __float2bfloat16(c);
            bf16 sb16 = __float2bfloat16(s);
            tc[kr][tx] = cb16;
            ts[kr][tx] = sb16;
            g_Bc[((size_t)b*KK + k)*NN + n0 + tx] = cb16;
            g_Bs[((size_t)b*KK + k)*NN + n0 + tx] = sb16;
        }
        __syncthreads();
        #pragma unroll
        for (int jj = 0; jj < 4; jj++) {
            int nr = ty*4 + jj;
            int n = n0 + nr;
            g_BcT[((size_t)b*NN + n)*KK + k0 + tx] = tc[tx][nr];
            g_BsT[((size_t)b*NN + n)*KK + k0 + tx] = ts[tx][nr];
        }
        __syncthreads();
    }
}

// -------- K2: fc0 --------
__global__ void k_fc0(const float* __restrict__ x, const float* __restrict__ w,
                      const float* __restrict__ bias) {
    int n = blockIdx.x * blockDim.x + threadIdx.x;
    int c = blockIdx.y;
    int b = blockIdx.z;
    const float* xp = x + ((size_t)b * NN + n) * INDIM;
    float acc = bias[c]
              + xp[0] * w[0*CC + c]
              + xp[1] * w[1*CC + c]
              + xp[2] * w[2*CC + c];
    size_t o = ((size_t)b*CC + c) * NN + n;
    g_h[0][o] = acc;
    g_hwb[o]  = __float2bfloat16(acc * g_wqn[b*NN + n]);
}

// -------- K2b: x0h --------
__global__ void k_x0h() {
    int bc = blockIdx.x;
    const bf162* p = reinterpret_cast<const bf162*>(g_hwb + (size_t)bc * NN);
    float acc = 0.f;
    for (int n = threadIdx.x; n < NN/2; n += 256) {
        float2 v = __bfloat1622float2(p[n]);
        acc += v.x + v.y;
    }
    __shared__ float red[256];
    red[threadIdx.x] = acc;
    __syncthreads();
    for (int s = 128; s > 0; s >>= 1) {
        if (threadIdx.x < s) red[threadIdx.x] += red[threadIdx.x + s];
        __syncthreads();
    }
    if (threadIdx.x == 0) g_x0h[bc] = red[0];
}

// -------- K3: forward dual GEMM, bf16 TC, split-N --------
__global__ void k_fwd_tc() {
    __shared__ bf16 As[32][72];
    __shared__ bf16 Bsm[2][64][72];
    int z   = blockIdx.z;
    int b   = z >> 1;
    int s   = z & 1;
    int m0  = blockIdx.y * 32;
    int ko0 = blockIdx.x * 64;
    int tid = threadIdx.x;
    int lane = tid & 31, wid = tid >> 5;
    int wm = wid >> 2, wn = wid & 3;
    int g = lane >> 2, tig = lane & 3;
    float acc[2][2][4] = {};
    const bf16* A  = g_hwb + ((size_t)b*CC + m0) * NN + s * (NN/FWD_S);
    const bf16* Bc = g_Bc  + ((size_t)b*KK + ko0) * NN + s * (NN/FWD_S);
    const bf16* Bs = g_Bs  + ((size_t)b*KK + ko0) * NN + s * (NN/FWD_S);
    int arow = tid >> 3, ac8 = (tid & 7) * 8;
    for (int r0 = 0; r0 < NN/FWD_S; r0 += 64) {
        *(uint4*)&As[arow][ac8] = *(const uint4*)&A[(size_t)arow*NN + r0 + ac8];
        #pragma unroll
        for (int t = 0; t < 2; t++) {
            int brow = (tid >> 3) + t*32;
            *(uint4*)&Bsm[0][brow][ac8] = *(const uint4*)&Bc[(size_t)brow*NN + r0 + ac8];
            *(uint4*)&Bsm[1][brow][ac8] = *(const uint4*)&Bs[(size_t)brow*NN + r0 + ac8];
        }
        __syncthreads();
        #pragma unroll
        for (int kk = 0; kk < 64; kk += 16) {
            uint32_t af[4];
            int m = wm * 16;
            af[0] = *(const uint32_t*)&As[m+g  ][kk + 2*tig    ];
            af[1] = *(const uint32_t*)&As[m+g+8][kk + 2*tig    ];
            af[2] = *(const uint32_t*)&As[m+g  ][kk + 2*tig + 8];
            af[3] = *(const uint32_t*)&As[m+g+8][kk + 2*tig + 8];
            #pragma unroll
            for (int p = 0; p < 2; p++) {
                #pragma unroll
                for (int ns = 0; ns < 2; ns++) {
                    int n = wn * 16 + ns * 8;
                    uint32_t bf[2];
                    bf[0] = *(const uint32_t*)&Bsm[p][n+g][kk + 2*tig    ];
                    bf[1] = *(const uint32_t*)&Bsm[p][n+g][kk + 2*tig + 8];
                    mma_bf16(acc[p][ns], af, bf);
                }
            }
        }
        __syncthreads();
    }
    #pragma unroll
    for (int ns = 0; ns < 2; ns++) {
        int m = m0 + wm*16 + g;
        int k = ko0 + wn*16 + ns*8 + tig*2;
        size_t o0 = ((size_t)b*CC + m)*KK + k;
        size_t o1 = ((size_t)b*CC + m + 8)*KK + k;
        g_pc[s][o0]   = acc[0][ns][0];
        g_pc[s][o0+1] = acc[0][ns][1];
        g_pc[s][o1]   = acc[0][ns][2];
        g_pc[s][o1+1] = acc[0][ns][3];
        g_ps[s][o0]   = acc[1][ns][0];
        g_ps[s][o0+1] = acc[1][ns][1];
        g_ps[s][o1]   = acc[1][ns][2];
        g_ps[s][o1+1] = acc[1][ns][3];
    }
}

__global__ void k_fwd_red() {
    int i = (blockIdx.x * 256 + threadIdx.x) * 4;
    float4 c0 = *(const float4*)&g_pc[0][i];
    float4 c1 = *(const float4*)&g_pc[1][i];
    float4 s0 = *(const float4*)&g_ps[0][i];
    float4 s1 = *(const float4*)&g_ps[1][i];
    float4 c, s;
    c.x = c0.x+c1.x; c.y = c0.y+c1.y; c.z = c0.z+c1.z; c.w = c0.w+c1.w;
    s.x = s0.x+s1.x; s.y = s0.y+s1.y; s.z = s0.z+s1.z; s.w = s0.w+s1.w;
    *(float4*)&g_xch[i] = c;
    *(float4*)&g_xsp[i] = s;
}

// -------- K4: mode mix --------
__global__ void k_mix_all(const float* __restrict__ wc, const float* __restrict__ ws) {
    int o = blockIdx.x;
    int l = blockIdx.y;
    int k = threadIdx.x * 4;
    const float inv_nf = 1.0f / (float)NFF;
    float4 accc[BB], accs[BB];
    #pragma unroll
    for (int b = 0; b < BB; b++) {
        accc[b] = make_float4(0.f,0.f,0.f,0.f);
        accs[b] = make_float4(0.f,0.f,0.f,0.f);
    }
    const float* wcp = wc + (((size_t)l*CC)*CC + o)*KK + k;
    const float* wsp = ws + (((size_t)l*CC)*CC + o)*KK + k;
    #pragma unroll 4
    for (int i = 0; i < CC; i++) {
        float4 wcv = *(const float4*)(wcp + (size_t)i*CC*KK);
        float4 wsv = *(const float4*)(wsp + (size_t)i*CC*KK);
        #pragma unroll
        for (int b = 0; b < BB; b++) {
            float4 xc = *(const float4*)(g_xch + ((size_t)b*CC + i)*KK + k);
            float4 xs = *(const float4*)(g_xsp + ((size_t)b*CC + i)*KK + k);
            accc[b].x += xc.x*wcv.x + xs.x*wsv.x;
            accc[b].y += xc.y*wcv.y + xs.y*wsv.y;
            accc[b].z += xc.z*wcv.z + xs.z*wsv.z;
            accc[b].w += xc.w*wcv.w + xs.w*wsv.w;
            accs[b].x += xc.x*wsv.x - xs.x*wcv.x;
            accs[b].y += xc.y*wsv.y - xs.y*wcv.y;
            accs[b].z += xc.z*wsv.z - xs.z*wcv.z;
            accs[b].w += xc.w*wsv.w - xs.w*wcv.w;
        }
    }
    #pragma unroll
    for (int b = 0; b < BB; b++) {
        size_t o4 = ((size_t)b*CC + o)*KK + k;
        bf162* fa = reinterpret_cast<bf162*>(&g_fAb[l][o4]);
        bf162* fb = reinterpret_cast<bf162*>(&g_fBb[l][o4]);
        fa[0] = __floats2bfloat162_rn( 2.0f*inv_nf*accc[b].x,  2.0f*inv_nf*accc[b].y);
        fa[1] = __floats2bfloat162_rn( 2.0f*inv_nf*accc[b].z,  2.0f*inv_nf*accc[b].w);
        fb[0] = __floats2bfloat162_rn(-2.0f*inv_nf*accs[b].x, -2.0f*inv_nf*accs[b].y);
        fb[1] = __floats2bfloat162_rn(-2.0f*inv_nf*accs[b].z, -2.0f*inv_nf*accs[b].w);
    }
}

// -------- K4b: f0h --------
__global__ void k_f0h_all(const float* __restrict__ w0, const float* __restrict__ convb) {
    int l = blockIdx.x;
    int t = threadIdx.x;
    int b = t >> 7, o = t & 127;
    float acc = 0.f;
    #pragma unroll 4
    for (int i = 0; i < CC; i++)
        acc += g_x0h[b*CC + i] * __ldg(&w0[((size_t)l*CC + i)*CC + o]);
    g_f0h[l][t] = acc * (1.0f / (float)NFF) + convb[l*CC + o];
}

// -------- K5a: inverse spectral GEMM --------
__global__ void k_inv_spec_all() {
    __shared__ bf16 As[2][64][40];
    __shared__ bf16 Bsm[2][128][40];
    int z  = blockIdx.z;
    int b  = z & (BB-1);
    int l  = z >> 2;
    int m0 = blockIdx.y * 64;
    int n0 = blockIdx.x * 128;
    int tid = threadIdx.x;
    int lane = tid & 31, wid = tid >> 5;
    int wm = wid >> 2, wn = wid & 3;
    int g = lane >> 2, tig = lane & 3;
    float acc[2][4][4] = {};
    const bf16* fA = g_fAb[l] + ((size_t)b*CC + m0)*KK;
    const bf16* fB = g_fBb[l] + ((size_t)b*CC + m0)*KK;
    const bf16* BcT = g_BcT + ((size_t)b*NN + n0)*KK;
    const bf16* BsT = g_BsT + ((size_t)b*NN + n0)*KK;
    int arow = tid >> 2, ac8 = (tid & 3) * 8;
    for (int r0 = 0; r0 < KK; r0 += 32) {
        *(uint4*)&As[0][arow][ac8] = *(const uint4*)&fA[(size_t)arow*KK + r0 + ac8];
        *(uint4*)&As[1][arow][ac8] = *(const uint4*)&fB[(size_t)arow*KK + r0 + ac8];
        #pragma unroll
        for (int t = 0; t < 2; t++) {
            int brow = (tid >> 2) + t*64;
            *(uint4*)&Bsm[0][brow][ac8] = *(const uint4*)&BcT[(size_t)brow*KK + r0 + ac8];
            *(uint4*)&Bsm[1][brow][ac8] = *(const uint4*)&BsT[(size_t)brow*KK + r0 + ac8];
        }
        __syncthreads();
        #pragma unroll
        for (int kk = 0; kk < 32; kk += 16) {
            #pragma unroll
            for (int p = 0; p < 2; p++) {
                uint32_t af[2][4];
                #pragma unroll
                for (int ms = 0; ms < 2; ms++) {
                    int m = wm*32 + ms*16;
                    af[ms][0] = *(const uint32_t*)&As[p][m+g  ][kk + 2*tig    ];
                    af[ms][1] = *(const uint32_t*)&As[p][m+g+8][kk + 2*tig    ];
                    af[ms][2] = *(const uint32_t*)&As[p][m+g  ][kk + 2*tig + 8];
                    af[ms][3] = *(const uint32_t*)&As[p][m+g+8][kk + 2*tig + 8];
                }
                #pragma unroll
                for (int ns = 0; ns < 4; ns++) {
                    int n = wn*32 + ns*8;
                    uint32_t bf[2];
                    bf[0] = *(const uint32_t*)&Bsm[p][n+g][kk + 2*tig    ];
                    bf[1] = *(const uint32_t*)&Bsm[p][n+g][kk + 2*tig + 8];
                    #pragma unroll
                    for (int ms = 0; ms < 2; ms++)
                        mma_bf16(acc[ms][ns], af[ms], bf);
                }
            }
        }
        __syncthreads();
    }
    bf16* X1 = g_x1b[l] + (size_t)b*CC*NN;
    #pragma unroll
    for (int ms = 0; ms < 2; ms++) {
        #pragma unroll
        for (int ns = 0; ns < 4; ns++) {
            int m = m0 + wm*32 + ms*16 + g;
            int n = n0 + wn*32 + ns*8 + tig*2;
            *reinterpret_cast<bf162*>(&X1[(size_t)m*NN + n]) =
                __floats2bfloat162_rn(acc[ms][ns][0], acc[ms][ns][1]);
            *reinterpret_cast<bf162*>(&X1[(size_t)(m+8)*NN + n]) =
                __floats2bfloat162_rn(acc[ms][ns][2], acc[ms][ns][3]);
        }
    }
}

// -------- K5b: conv via 3xTF32 + epilogue --------
__global__ void k_conv_tc(const float* __restrict__ convw, int l, int cur) {
    __shared__ float Ah[64][20], Al[64][20];
    __shared__ float Bh[16][132], Bl[16][132];
    int b  = blockIdx.z;
    int m0 = blockIdx.y * 64;
    int n0 = blockIdx.x * 128;
    int tid = threadIdx.x;
    int lane = tid & 31, wid = tid >> 5;
    int wm = wid >> 2, wn = wid & 3;
    int g = lane >> 2, tig = lane & 3;
    float acc[2][4][4] = {};
    const float* W = convw + (size_t)l*CC*CC + (size_t)m0*CC;
    const float* H = g_h[cur] + (size_t)b*CC*NN;
    int arow = tid >> 2, ac4 = (tid & 3) * 4;
    for (int r0 = 0; r0 < CC; r0 += 16) {
        float4 va = *(const float4*)&W[(size_t)arow*CC + r0 + ac4];
        float h0,l0,h1,l1,h2,l2,h3,l3;
        split_tf32(va.x, h0, l0); split_tf32(va.y, h1, l1);
        split_tf32(va.z, h2, l2); split_tf32(va.w, h3, l3);
        Ah[arow][ac4] = h0; Ah[arow][ac4+1] = h1; Ah[arow][ac4+2] = h2; Ah[arow][ac4+3] = h3;
        Al[arow][ac4] = l0; Al[arow][ac4+1] = l1; Al[arow][ac4+2] = l2; Al[arow][ac4+3] = l3;
        #pragma unroll
        for (int t = 0; t < 2; t++) {
            int idx = tid + t*256;
            int brow = idx >> 5, bc4 = (idx & 31) * 4;
            float4 vb = *(const float4*)&H[(size_t)(r0+brow)*NN + n0 + bc4];
            float bh0,bl0,bh1,bl1,bh2,bl2,bh3,bl3;
            split_tf32(vb.x, bh0, bl0); split_tf32(vb.y, bh1, bl1);
            split_tf32(vb.z, bh2, bl2); split_tf32(vb.w, bh3, bl3);
            Bh[brow][bc4] = bh0; Bh[brow][bc4+1] = bh1; Bh[brow][bc4+2] = bh2; Bh[brow][bc4+3] = bh3;
            Bl[brow][bc4] = bl0; Bl[brow][bc4+1] = bl1; Bl[brow][bc4+2] = bl2; Bl[brow][bc4+3] = bl3;
        }
        __syncthreads();
        #pragma unroll
        for (int kk = 0; kk < 16; kk += 8) {
            uint32_t afh[2][4], afl[2][4];
            #pragma unroll
            for (int ms = 0; ms < 2; ms++) {
                int m = wm*32 + ms*16;
                afh[ms][0] = __float_as_uint(Ah[m+g  ][kk+tig  ]);
                afh[ms][1] = __float_as_uint(Ah[m+g+8][kk+tig  ]);
                afh[ms][2] = __float_as_uint(Ah[m+g  ][kk+tig+4]);
                afh[ms][3] = __float_as_uint(Ah[m+g+8][kk+tig+4]);
                afl[ms][0] = __float_as_uint(Al[m+g  ][kk+tig  ]);
                afl[ms][1] = __float_as_uint(Al[m+g+8][kk+tig  ]);
                afl[ms][2] = __float_as_uint(Al[m+g  ][kk+tig+4]);
                afl[ms][3] = __float_as_uint(Al[m+g+8][kk+tig+4]);
            }
            #pragma unroll
            for (int ns = 0; ns < 4; ns++) {
                int n = wn*32 + ns*8;
                uint32_t bfh[2], bfl[2];
                bfh[0] = __float_as_uint(Bh[kk+tig  ][n+g]);
                bfh[1] = __float_as_uint(Bh[kk+tig+4][n+g]);
                bfl[0] = __float_as_uint(Bl[kk+tig  ][n+g]);
                bfl[1] = __float_as_uint(Bl[kk+tig+4][n+g]);
                #pragma unroll
                for (int ms = 0; ms < 2; ms++) {
                    mma_tf32(acc[ms][ns], afh[ms], bfh);
                    mma_tf32(acc[ms][ns], afh[ms], bfl);
                    mma_tf32(acc[ms][ns], afl[ms], bfh);
                }
            }
        }
        __syncthreads();
    }
    int nxt = cur ^ 1;
    const bf16* X1 = g_x1b[l] + (size_t)b*CC*NN;
    float* Hn = g_h[nxt] + (size_t)b*CC*NN;
    #pragma unroll
    for (int ms = 0; ms < 2; ms++) {
        #pragma unroll
        for (int ns = 0; ns < 4; ns++) {
            int m = m0 + wm*32 + ms*16 + g;
            int n = n0 + wn*32 + ns*8 + tig*2;
            float bias0 = g_f0h[l][b*CC + m];
            float bias1 = g_f0h[l][b*CC + m + 8];
            float2 x1a = __bfloat1622float2(*reinterpret_cast<const bf162*>(&X1[(size_t)m*NN + n]));
            float2 x1b = __bfloat1622float2(*reinterpret_cast<const bf162*>(&X1[(size_t)(m+8)*NN + n]));
            float v0 = acc[ms][ns][0] + bias0 + x1a.x;
            float v1 = acc[ms][ns][1] + bias0 + x1a.y;
            float v2 = acc[ms][ns][2] + bias1 + x1b.x;
            float v3 = acc[ms][ns][3] + bias1 + x1b.y;
            if (l < LL - 1) {
                v0 = gelu_exact(v0); v1 = gelu_exact(v1);
                v2 = gelu_exact(v2); v3 = gelu_exact(v3);
            }
            Hn[(size_t)m*NN + n]         = v0;
            Hn[(size_t)m*NN + n + 1]     = v1;
            Hn[(size_t)(m+8)*NN + n]     = v2;
            Hn[(size_t)(m+8)*NN + n + 1] = v3;
        }
    }
}

// -------- K6: head --------
__global__ void k_head(const float* __restrict__ w1, const float* __restrict__ b1,
                       const float* __restrict__ w2, const float* __restrict__ b2,
                       float* __restrict__ out, int cur) {
    __shared__ float sh[CC][32];
    __shared__ float red[CC][33];
    int b  = blockIdx.y;
    int n0 = blockIdx.x * 32;
    int f = threadIdx.x;
    const float* H = g_h[cur] + (size_t)b*CC*NN + n0;
    #pragma unroll 4
    for (int c4 = 0; c4 < CC; c4 += 4) {
        int row = c4 + (f >> 5);
        int col = f & 31;
        sh[row][col] = H[(size_t)row*NN + col];
    }
    __syncthreads();
    float acc[32];
    float bv = b1[f];
    #pragma unroll
    for (int j = 0; j < 32; j++) acc[j] = bv;
    for (int c = 0; c < CC; c++) {
        float w = __ldg(&w1[(size_t)c*FCD + f]);
        #pragma unroll
        for (int j = 0; j < 32; j++) acc[j] += sh[c][j] * w;
    }
    float w2f = __ldg(&w2[f]);
    #pragma unroll
    for (int j = 0; j < 32; j++)
        red[f][j] = gelu_exact(acc[j]) * w2f;
    __syncthreads();
    if (f < 32) {
        float s = b2[0];
        #pragma unroll 8
        for (int q = 0; q < CC; q++) s += red[q][f];
        out[(size_t)b*NN + n0 + f] = s;
    }
}

// -------- launch --------
extern "C" void kernel_launch(void* const* d_in, const int* in_sizes, int n_in,
                              void* d_out, int out_size) {
    (void)in_sizes; (void)n_in; (void)out_size;
    const float* x     = (const float*)d_in[0];
    const float* xf    = (const float*)d_in[1];
    const int*   ind   = (const int*)  d_in[2];
    const float* modes = (const float*)d_in[3];
    const float* fc0_w = (const float*)d_in[4];
    const float* fc0_b = (const float*)d_in[5];
    const float* wc    = (const float*)d_in[6];
    const float* ws    = (const float*)d_in[7];
    const float* w0    = (const float*)d_in[8];
    const float* convw = (const float*)d_in[9];
    const float* convb = (const float*)d_in[10];
    const float* fc1_w = (const float*)d_in[11];
    const float* fc1_b = (const float*)d_in[12];
    const float* fc2_w = (const float*)d_in[13];
    const float* fc2_b = (const float*)d_in[14];
    float* out = (float*)d_out;

    k_wqn<<<BB*NN/256, 256>>>(xf, ind);
    dim3 g1(NN/32, BB);
    k_basis<<<g1, 256>>>(xf, ind, modes);

    dim3 g2(NN/256, CC, BB);
    k_fc0<<<g2, 256>>>(x, fc0_w, fc0_b);

    k_x0h<<<BB*CC, 256>>>();
    dim3 g3(KK/64, CC/32, BB*FWD_S);
    k_fwd_tc<<<g3, 256>>>();
    k_fwd_red<<<BB*CC*KK/1024, 256>>>();

    dim3 g4(CC, LL);
    k_mix_all<<<g4, 128>>>(wc, ws);
    k_f0h_all<<<LL, BB*CC>>>(w0, convb);
    dim3 g5(NN/128, CC/64, BB*LL);
    k_inv_spec_all<<<g5, 256>>>();

    int cur = 0;
    for (int l = 0; l < LL; l++) {
        dim3 g6(NN/128, CC/64, BB);
        k_conv_tc<<<g6, 256>>>(convw, l, cur);
        cur ^= 1;
    }

    dim3 g7(NN/32, BB);
    k_head<<<g7, 128>>>(fc1_w, fc1_b, fc2_w, fc2_b, out, cur);
}